// round 3
// baseline (speedup 1.0000x reference)
#include <cuda_runtime.h>

// QINCo: D=128, M=8 (1 + 7 neural steps), K=256 codes, L=2 MLP layers, H=256, BS=1024
namespace {
constexpr int D_  = 128;
constexpr int K_  = 256;
constexpr int M_  = 8;
constexpr int H_  = 256;
constexpr int BS_ = 1024;
constexpr int NR  = BS_ * K_;          // 262144 candidate rows per step

constexpr int OUT_CODES = BS_ * D_;             // 131072
constexpr int OUT_SIDE  = OUT_CODES + BS_ * M_; // 139264
constexpr int SIDE_SZ   = BS_ * D_;             // per side tensor
}

// ---- scratch (device globals: allocation-free) ----
__device__ __align__(128) float g_z[NR * D_];            // candidate vectors
__device__ __align__(128) float g_h[NR * H_];            // MLP hidden (layer 1 only)
__device__ __align__(128) float g_cbz[(M_-1) * K_ * D_]; // cb + cb@Wz^T + bc
__device__ __align__(128) float g_P1[(M_-1) * K_ * H_];  // cbz @ W1_0^T  (weight-only)
__device__ __align__(128) float g_y[BS_ * D_];           // xhat @ Wx^T
__device__ __align__(128) float g_Q1[BS_ * H_];          // y @ W1_0^T
__device__ __align__(128) float g_xa[BS_ * D_];          // xhat ping
__device__ __align__(128) float g_xb[BS_ * D_];          // xhat pong

__device__ __forceinline__ void warp_red2(float& a, float& b) {
#pragma unroll
    for (int o = 16; o; o >>= 1) {
        a += __shfl_xor_sync(0xffffffffu, a, o);
        b += __shfl_xor_sync(0xffffffffu, b, o);
    }
}

// ---- cbz[m][k][:] = cb + cb @ Wz^T + bc  (Wz = Wc[m][:, :D]) ----
__global__ void k_cbz(const float* __restrict__ cbs, const float* __restrict__ Wc,
                      const float* __restrict__ bc) {
    int r = blockIdx.x;            // 0..7*256-1
    int m = r >> 8, k = r & 255;
    __shared__ float cb[D_];
    int d = threadIdx.x;
    cb[d] = cbs[(m * K_ + k) * D_ + d];
    __syncthreads();
    const float* wrow = Wc + (m * D_ + d) * (2 * D_);   // Wz part: cols [0,128)
    float acc = cb[d] + bc[m * D_ + d];
#pragma unroll 8
    for (int j = 0; j < D_; ++j) acc = fmaf(cb[j], wrow[j], acc);
    g_cbz[r * D_ + d] = acc;
}

// ---- P1[m][k][h] = cbz[m][k] @ W1[m][0]^T  (weight-only precompute) ----
__global__ void k_p1(const float* __restrict__ W1) {
    int r = blockIdx.x;            // (m,k)
    int m = r >> 8;
    __shared__ float cb[D_];
    int h = threadIdx.x;           // 256 threads
    if (h < D_) cb[h] = g_cbz[r * D_ + h];
    __syncthreads();
    const float* wrow = W1 + (m * 2) * H_ * D_ + h * D_;   // W1[m][0][h][:]
    float acc = 0.f;
#pragma unroll 8
    for (int j = 0; j < D_; ++j) acc = fmaf(cb[j], wrow[j], acc);
    g_P1[r * H_ + h] = acc;
}

// ---- y[b][:] = xhat @ Wx^T  (Wx = Wc[m][:, D:2D]) ----
__global__ void k_y(const float* __restrict__ Wc, int m, int ping) {
    const float* xin = ping ? g_xb : g_xa;
    int b = blockIdx.x, d = threadIdx.x;
    __shared__ float xh[D_];
    xh[d] = xin[b * D_ + d];
    __syncthreads();
    const float* wrow = Wc + (m * D_ + d) * (2 * D_) + D_;
    float acc = 0.f;
#pragma unroll 8
    for (int j = 0; j < D_; ++j) acc = fmaf(xh[j], wrow[j], acc);
    g_y[b * D_ + d] = acc;
}

// ---- Q1[b][h] = y[b] @ W1[m][0]^T ----
__global__ void k_q1(const float* __restrict__ W1, int m) {
    int b = blockIdx.x, h = threadIdx.x;   // 256 threads
    __shared__ float ys[D_];
    if (h < D_) ys[h] = g_y[b * D_ + h];
    __syncthreads();
    const float* wrow = W1 + (m * 2) * H_ * D_ + h * D_;
    float acc = 0.f;
#pragma unroll 8
    for (int j = 0; j < D_; ++j) acc = fmaf(ys[j], wrow[j], acc);
    g_Q1[b * H_ + h] = acc;
}

// ============ double-buffered SGEMM core (128x128 tile, 8x8 microtile) ============
template <bool RELU, bool ACC, int K, int O>
__device__ __forceinline__ void gemm_std(const float* __restrict__ A,
                                         const float* __restrict__ W,
                                         float* __restrict__ C) {
    __shared__ float As[2][8][128];
    __shared__ float Bs[2][8][128];
    const int tid  = threadIdx.x;
    const int cRow = blockIdx.y * 128;
    const int cCol = blockIdx.x * 128;
    const int tRow = (tid >> 4) * 8;
    const int tCol = (tid & 15) * 8;
    const int rA = tid >> 1;
    const int cA = (tid & 1) * 4;

    float acc[8][8] = {};
    const float* Ap = A + (cRow + rA) * K + cA;
    const float* Wp = W + (cCol + rA) * K + cA;

    float4 a4 = *(const float4*)Ap;
    float4 b4 = *(const float4*)Wp;
    As[0][cA + 0][rA] = a4.x; As[0][cA + 1][rA] = a4.y;
    As[0][cA + 2][rA] = a4.z; As[0][cA + 3][rA] = a4.w;
    Bs[0][cA + 0][rA] = b4.x; Bs[0][cA + 1][rA] = b4.y;
    Bs[0][cA + 2][rA] = b4.z; Bs[0][cA + 3][rA] = b4.w;
    __syncthreads();

    constexpr int NT = K / 8;
    int buf = 0;
#pragma unroll 1
    for (int it = 0; it < NT; ++it) {
        float4 an, bn;
        if (it + 1 < NT) {
            an = *(const float4*)(Ap + (it + 1) * 8);
            bn = *(const float4*)(Wp + (it + 1) * 8);
        }
#pragma unroll
        for (int kk = 0; kk < 8; ++kk) {
            float rm[8], rn[8];
            *(float4*)(rm)     = *(const float4*)&As[buf][kk][tRow];
            *(float4*)(rm + 4) = *(const float4*)&As[buf][kk][tRow + 4];
            *(float4*)(rn)     = *(const float4*)&Bs[buf][kk][tCol];
            *(float4*)(rn + 4) = *(const float4*)&Bs[buf][kk][tCol + 4];
#pragma unroll
            for (int i = 0; i < 8; ++i)
#pragma unroll
                for (int j = 0; j < 8; ++j)
                    acc[i][j] = fmaf(rm[i], rn[j], acc[i][j]);
        }
        if (it + 1 < NT) {
            int nb = buf ^ 1;
            As[nb][cA + 0][rA] = an.x; As[nb][cA + 1][rA] = an.y;
            As[nb][cA + 2][rA] = an.z; As[nb][cA + 3][rA] = an.w;
            Bs[nb][cA + 0][rA] = bn.x; Bs[nb][cA + 1][rA] = bn.y;
            Bs[nb][cA + 2][rA] = bn.z; Bs[nb][cA + 3][rA] = bn.w;
            __syncthreads();
            buf = nb;
        }
    }

#pragma unroll
    for (int i = 0; i < 8; ++i) {
        float* cp = C + (cRow + tRow + i) * O + cCol + tCol;
#pragma unroll
        for (int j4 = 0; j4 < 8; j4 += 4) {
            float4 v = make_float4(acc[i][j4], acc[i][j4 + 1], acc[i][j4 + 2], acc[i][j4 + 3]);
            if (ACC) {
                float4 o = *(const float4*)(cp + j4);
                v.x += o.x; v.y += o.y; v.z += o.z; v.w += o.w;
            }
            if (RELU) {
                v.x = fmaxf(v.x, 0.f); v.y = fmaxf(v.y, 0.f);
                v.z = fmaxf(v.z, 0.f); v.w = fmaxf(v.w, 0.f);
            }
            *(float4*)(cp + j4) = v;
        }
    }
}

__global__ void __launch_bounds__(256) k_gemm1(const float* __restrict__ W1) {
    gemm_std<true, false, D_, H_>(g_z, W1, g_h);      // h = relu(z @ W1^T)  (layer 1)
}
__global__ void __launch_bounds__(256) k_gemm2(const float* __restrict__ W2) {
    gemm_std<false, true, H_, D_>(g_h, W2, g_z);      // z += h @ W2^T       (layer 1)
}

// ---- fused layer-0 GEMM2: z1[(b,k),d] = (cbz[k]+y[b]) + relu(P1[k]+Q1[b]) @ W2_0^T ----
// A operand (h0) is generated on the fly from L2-resident P1/Q1; base folded in epilogue.
__global__ void __launch_bounds__(256) k_gemm2_l0(const float* __restrict__ W2, int m) {
    constexpr int K = H_;   // 256
    constexpr int O = D_;   // 128
    __shared__ float As[2][8][128];
    __shared__ float Bs[2][8][128];
    const int tid  = threadIdx.x;
    const int cRow = blockIdx.y * 128;       // cCol = 0 (O=128, grid.x=1)
    const int tRow = (tid >> 4) * 8;
    const int tCol = (tid & 15) * 8;
    const int rA = tid >> 1;
    const int cA = (tid & 1) * 4;

    const int rGlob = cRow + rA;
    const int bb = rGlob >> 8;               // batch index of loaded row
    const int kk_ = rGlob & 255;             // code index of loaded row
    const float* Pp = g_P1 + (m * K_ + kk_) * H_ + cA;
    const float* Qp = g_Q1 + bb * H_ + cA;
    const float* Wp = W2 + rA * K + cA;

    float acc[8][8] = {};

    float4 p = *(const float4*)Pp;
    float4 q = *(const float4*)Qp;
    float4 b4 = *(const float4*)Wp;
    float4 a4 = make_float4(fmaxf(p.x + q.x, 0.f), fmaxf(p.y + q.y, 0.f),
                            fmaxf(p.z + q.z, 0.f), fmaxf(p.w + q.w, 0.f));
    As[0][cA + 0][rA] = a4.x; As[0][cA + 1][rA] = a4.y;
    As[0][cA + 2][rA] = a4.z; As[0][cA + 3][rA] = a4.w;
    Bs[0][cA + 0][rA] = b4.x; Bs[0][cA + 1][rA] = b4.y;
    Bs[0][cA + 2][rA] = b4.z; Bs[0][cA + 3][rA] = b4.w;
    __syncthreads();

    constexpr int NT = K / 8;   // 32
    int buf = 0;
#pragma unroll 1
    for (int it = 0; it < NT; ++it) {
        float4 an, bn;
        if (it + 1 < NT) {
            float4 pn = *(const float4*)(Pp + (it + 1) * 8);
            float4 qn = *(const float4*)(Qp + (it + 1) * 8);
            an = make_float4(fmaxf(pn.x + qn.x, 0.f), fmaxf(pn.y + qn.y, 0.f),
                             fmaxf(pn.z + qn.z, 0.f), fmaxf(pn.w + qn.w, 0.f));
            bn = *(const float4*)(Wp + (it + 1) * 8);
        }
#pragma unroll
        for (int kk = 0; kk < 8; ++kk) {
            float rm[8], rn[8];
            *(float4*)(rm)     = *(const float4*)&As[buf][kk][tRow];
            *(float4*)(rm + 4) = *(const float4*)&As[buf][kk][tRow + 4];
            *(float4*)(rn)     = *(const float4*)&Bs[buf][kk][tCol];
            *(float4*)(rn + 4) = *(const float4*)&Bs[buf][kk][tCol + 4];
#pragma unroll
            for (int i = 0; i < 8; ++i)
#pragma unroll
                for (int j = 0; j < 8; ++j)
                    acc[i][j] = fmaf(rm[i], rn[j], acc[i][j]);
        }
        if (it + 1 < NT) {
            int nb = buf ^ 1;
            As[nb][cA + 0][rA] = an.x; As[nb][cA + 1][rA] = an.y;
            As[nb][cA + 2][rA] = an.z; As[nb][cA + 3][rA] = an.w;
            Bs[nb][cA + 0][rA] = bn.x; Bs[nb][cA + 1][rA] = bn.y;
            Bs[nb][cA + 2][rA] = bn.z; Bs[nb][cA + 3][rA] = bn.w;
            __syncthreads();
            buf = nb;
        }
    }

    // epilogue: add base z0 = cbz[m][k] + y[b]
#pragma unroll
    for (int i = 0; i < 8; ++i) {
        int r = cRow + tRow + i;
        int eb = r >> 8, ek = r & 255;
        const float* cbzr = g_cbz + (m * K_ + ek) * D_ + tCol;
        const float* yr   = g_y + eb * D_ + tCol;
        float* cp = g_z + r * O + tCol;
#pragma unroll
        for (int j4 = 0; j4 < 8; j4 += 4) {
            float4 v = make_float4(acc[i][j4], acc[i][j4 + 1], acc[i][j4 + 2], acc[i][j4 + 3]);
            float4 c = *(const float4*)(cbzr + j4);
            float4 y = *(const float4*)(yr + j4);
            v.x += c.x + y.x; v.y += c.y + y.y;
            v.z += c.z + y.z; v.w += c.w + y.w;
            *(float4*)(cp + j4) = v;
        }
    }
}

// ---- step 0: argmin_k |x - cb0[k]|^2; write xhat, side0, code0 ----
__global__ void k_step0(const float* __restrict__ x, const float* __restrict__ cb0,
                        float* __restrict__ out) {
    int b = blockIdx.x, t = threadIdx.x;
    int w = t >> 5, lane = t & 31;
    __shared__ float4 xs[32];
    __shared__ float  sd[256];
    __shared__ int    si[256];
    if (t < 32) xs[t] = ((const float4*)x)[b * 32 + t];
    __syncthreads();
    float4 xv = xs[lane];
    for (int i = 0; i < 32; ++i) {
        int k = w * 32 + i;
        float4 c = ((const float4*)cb0)[k * 32 + lane];
        float a1 = c.x * c.x + c.y * c.y + c.z * c.z + c.w * c.w;
        float a2 = xv.x * c.x + xv.y * c.y + xv.z * c.z + xv.w * c.w;
        warp_red2(a1, a2);
        if (lane == 0) sd[k] = a1 - 2.f * a2;
    }
    si[t] = t;
    __syncthreads();
    for (int s = 128; s; s >>= 1) {
        if (t < s) {
            float o = sd[t + s]; int oi = si[t + s];
            if (o < sd[t] || (o == sd[t] && oi < si[t])) { sd[t] = o; si[t] = oi; }
        }
        __syncthreads();
    }
    int kb = si[0];
    if (t < D_) {
        float v = cb0[kb * D_ + t];
        g_xa[b * D_ + t] = v;
        out[OUT_SIDE + b * D_ + t] = v;       // side[0]
    }
    if (t == 0) out[OUT_CODES + b * M_] = (float)kb;
}

// ---- step m: zf = z + xhat; argmin_k (|zf|^2 - 2 x.zf); update xhat; emit outputs ----
__global__ void k_argupd(const float* __restrict__ x, float* __restrict__ out,
                         int m, int ping) {
    const float* xin = ping ? g_xb : g_xa;
    float*       xout = ping ? g_xa : g_xb;
    int b = blockIdx.x, t = threadIdx.x;
    int w = t >> 5, lane = t & 31;
    __shared__ float4 xs[32], hs[32];
    __shared__ float  sd[256];
    __shared__ int    si[256];
    if (t < 32) {
        xs[t] = ((const float4*)x)[b * 32 + t];
        hs[t] = ((const float4*)xin)[b * 32 + t];
    }
    __syncthreads();
    float4 xv = xs[lane], hv = hs[lane];
    const float4* zr = (const float4*)g_z + b * (K_ * 32);
    for (int i = 0; i < 32; ++i) {
        int k = w * 32 + i;
        float4 z = zr[k * 32 + lane];
        z.x += hv.x; z.y += hv.y; z.z += hv.z; z.w += hv.w;
        float a1 = z.x * z.x + z.y * z.y + z.z * z.z + z.w * z.w;
        float a2 = xv.x * z.x + xv.y * z.y + xv.z * z.z + xv.w * z.w;
        warp_red2(a1, a2);
        if (lane == 0) sd[k] = a1 - 2.f * a2;
    }
    si[t] = t;
    __syncthreads();
    for (int s = 128; s; s >>= 1) {
        if (t < s) {
            float o = sd[t + s]; int oi = si[t + s];
            if (o < sd[t] || (o == sd[t] && oi < si[t])) { sd[t] = o; si[t] = oi; }
        }
        __syncthreads();
    }
    int kb = si[0];
    if (t < D_) {
        float v = g_z[(b * K_ + kb) * D_ + t] + xin[b * D_ + t];
        xout[b * D_ + t] = v;
        out[OUT_SIDE + (m + 1) * SIDE_SZ + b * D_ + t] = v;  // side[m+1]
        if (m == M_ - 2) out[b * D_ + t] = v;                // final xhat
    }
    if (t == 0) out[OUT_CODES + b * M_ + m + 1] = (float)kb;
}

extern "C" void kernel_launch(void* const* d_in, const int* in_sizes, int n_in,
                              void* d_out, int out_size) {
    const float* x   = (const float*)d_in[0];
    const float* cb0 = (const float*)d_in[1];
    const float* cbs = (const float*)d_in[2];
    const float* Wc  = (const float*)d_in[3];
    const float* bc  = (const float*)d_in[4];
    const float* W1  = (const float*)d_in[5];
    const float* W2  = (const float*)d_in[6];
    float* out = (float*)d_out;

    // weight-only precomputes
    k_cbz<<<(M_ - 1) * K_, D_>>>(cbs, Wc, bc);
    k_p1<<<(M_ - 1) * K_, H_>>>(W1);
    k_step0<<<BS_, 256>>>(x, cb0, out);

    int ping = 0;   // xhat currently in g_xa
    for (int m = 0; m < M_ - 1; ++m) {
        k_y<<<BS_, D_>>>(Wc, m, ping);
        k_q1<<<BS_, H_>>>(W1, m);
        // layer 0 (GEMM1 eliminated algebraically; base + h0 fused here)
        k_gemm2_l0<<<dim3(1, NR / 128), 256>>>(W2 + (m * 2) * D_ * H_, m);
        // layer 1 (full GEMMs)
        k_gemm1<<<dim3(H_ / 128, NR / 128), 256>>>(W1 + (m * 2 + 1) * H_ * D_);
        k_gemm2<<<dim3(D_ / 128, NR / 128), 256>>>(W2 + (m * 2 + 1) * D_ * H_);
        k_argupd<<<BS_, 256>>>(x, out, m, ping);
        ping ^= 1;
    }
}

// round 5
// speedup vs baseline: 1.1041x; 1.1041x over previous
#include <cuda_runtime.h>
#include <stdint.h>

// QINCo: D=128, M=8, K=256, L=2, H=256, BS=1024
namespace {
constexpr int D_  = 128;
constexpr int K_  = 256;
constexpr int M_  = 8;
constexpr int H_  = 256;
constexpr int BS_ = 1024;
constexpr int NR  = BS_ * K_;                   // 262144

constexpr int OUT_CODES = BS_ * D_;             // 131072
constexpr int OUT_SIDE  = OUT_CODES + BS_ * M_; // 139264
constexpr int SIDE_SZ   = BS_ * D_;
}

// ---- device scratch (allocation-free) ----
__device__ __align__(128) float g_z[NR * D_];
__device__ __align__(128) float g_h[NR * H_];
__device__ __align__(128) float g_cbz[(M_-1) * K_ * D_];
__device__ __align__(128) float g_P1[(M_-1) * K_ * H_];
__device__ __align__(128) float g_y[BS_ * D_];
__device__ __align__(128) float g_Q1[BS_ * H_];
__device__ __align__(128) float g_xa[BS_ * D_];
__device__ __align__(128) float g_xb[BS_ * D_];

// ---- packed fp32 helpers (sm_100+ base target) ----
__device__ __forceinline__ uint64_t dup2(float x) {
    uint64_t r;
    asm("mov.b64 %0, {%1, %1};" : "=l"(r) : "f"(x));
    return r;
}
__device__ __forceinline__ void fma2(uint64_t& d, uint64_t a, uint64_t b) {
    asm("fma.rn.f32x2 %0, %1, %2, %0;" : "+l"(d) : "l"(a), "l"(b));
}
__device__ __forceinline__ float2 u2f(uint64_t v) {
    float2 r;
    asm("mov.b64 {%0, %1}, %2;" : "=f"(r.x), "=f"(r.y) : "l"(v));
    return r;
}
__device__ __forceinline__ void warp_red2(float& a, float& b) {
#pragma unroll
    for (int o = 16; o; o >>= 1) {
        a += __shfl_xor_sync(0xffffffffu, a, o);
        b += __shfl_xor_sync(0xffffffffu, b, o);
    }
}

// ============ f32x2 double-buffered SGEMM core (128x128 tile, 8x8 microtile) ============
// C[?,O] (+)= (relu?)(A[?,K] * Wrows^T), W row r has stride WS.
// EPIAB: C += A_tile + bias (for cbz precompute; requires O==K).
template <bool RELU, bool ACC, int K, int O, int WS, bool EPIAB>
__device__ __forceinline__ void gemm_core(const float* __restrict__ A,
                                          const float* __restrict__ W,
                                          float* __restrict__ C,
                                          const float* __restrict__ bias) {
    __shared__ float As[2][8][128];
    __shared__ float Bs[2][8][128];
    const int tid  = threadIdx.x;
    const int cRow = blockIdx.y * 128;
    const int cCol = blockIdx.x * 128;
    const int tRow = (tid >> 4) * 8;
    const int tCol = (tid & 15) * 8;
    const int rA = tid >> 1;
    const int cA = (tid & 1) * 4;

    uint64_t acc2[8][4] = {};
    const float* Ap = A + (cRow + rA) * K + cA;
    const float* Wp = W + (cCol + rA) * WS + cA;

    float4 a4 = *(const float4*)Ap;
    float4 b4 = *(const float4*)Wp;
    As[0][cA+0][rA]=a4.x; As[0][cA+1][rA]=a4.y; As[0][cA+2][rA]=a4.z; As[0][cA+3][rA]=a4.w;
    Bs[0][cA+0][rA]=b4.x; Bs[0][cA+1][rA]=b4.y; Bs[0][cA+2][rA]=b4.z; Bs[0][cA+3][rA]=b4.w;
    __syncthreads();

    constexpr int NT = K / 8;
    int buf = 0;
#pragma unroll 1
    for (int it = 0; it < NT; ++it) {
        float4 an, bn;
        if (it + 1 < NT) {
            an = *(const float4*)(Ap + (it + 1) * 8);
            bn = *(const float4*)(Wp + (it + 1) * 8);
        }
#pragma unroll
        for (int kk = 0; kk < 8; ++kk) {
            float rm[8];
            *(float4*)(rm)   = *(const float4*)&As[buf][kk][tRow];
            *(float4*)(rm+4) = *(const float4*)&As[buf][kk][tRow+4];
            uint64_t rn2[4];
            *(uint4*)(&rn2[0]) = *(const uint4*)&Bs[buf][kk][tCol];
            *(uint4*)(&rn2[2]) = *(const uint4*)&Bs[buf][kk][tCol+4];
#pragma unroll
            for (int i = 0; i < 8; ++i) {
                uint64_t am = dup2(rm[i]);
#pragma unroll
                for (int j = 0; j < 4; ++j) fma2(acc2[i][j], am, rn2[j]);
            }
        }
        if (it + 1 < NT) {
            int nb = buf ^ 1;
            As[nb][cA+0][rA]=an.x; As[nb][cA+1][rA]=an.y; As[nb][cA+2][rA]=an.z; As[nb][cA+3][rA]=an.w;
            Bs[nb][cA+0][rA]=bn.x; Bs[nb][cA+1][rA]=bn.y; Bs[nb][cA+2][rA]=bn.z; Bs[nb][cA+3][rA]=bn.w;
            __syncthreads();
            buf = nb;
        }
    }

#pragma unroll
    for (int i = 0; i < 8; ++i) {
        float vv[8];
#pragma unroll
        for (int j = 0; j < 4; ++j) {
            float2 t = u2f(acc2[i][j]);
            vv[2*j] = t.x; vv[2*j+1] = t.y;
        }
        float* cp = C + (cRow + tRow + i) * O + cCol + tCol;
#pragma unroll
        for (int j4 = 0; j4 < 8; j4 += 4) {
            float4 v = make_float4(vv[j4], vv[j4+1], vv[j4+2], vv[j4+3]);
            if (ACC) {
                float4 o = *(const float4*)(cp + j4);
                v.x += o.x; v.y += o.y; v.z += o.z; v.w += o.w;
            }
            if (EPIAB) {
                float4 av = *(const float4*)(A + (cRow + tRow + i) * K + cCol + tCol + j4);
                float4 bb = *(const float4*)(bias + cCol + tCol + j4);
                v.x += av.x + bb.x; v.y += av.y + bb.y;
                v.z += av.z + bb.z; v.w += av.w + bb.w;
            }
            if (RELU) {
                v.x = fmaxf(v.x, 0.f); v.y = fmaxf(v.y, 0.f);
                v.z = fmaxf(v.z, 0.f); v.w = fmaxf(v.w, 0.f);
            }
            *(float4*)(cp + j4) = v;
        }
    }
}

// ---- big GEMMs (layer 1) ----
__global__ void __launch_bounds__(256) k_gemm1(const float* __restrict__ W1l) {
    gemm_core<true, false, 128, 256, 128, false>(g_z, W1l, g_h, nullptr);   // h = relu(z @ W1^T)
}
__global__ void __launch_bounds__(256) k_gemm2(const float* __restrict__ W2l) {
    gemm_core<false, true, 256, 128, 256, false>(g_h, W2l, g_z, nullptr);   // z += h @ W2^T
}

// ---- precompute GEMMs ----
__global__ void __launch_bounds__(256) k_cbzg(const float* __restrict__ cbs,
                                              const float* __restrict__ Wc,
                                              const float* __restrict__ bc) {
    int m = blockIdx.z;   // grid (1, 2, 7)
    gemm_core<false, false, 128, 128, 256, true>(
        cbs + m * K_ * D_, Wc + m * D_ * 2 * D_, g_cbz + m * K_ * D_, bc + m * D_);
}
__global__ void __launch_bounds__(256) k_p1g(const float* __restrict__ W1) {
    int m = blockIdx.z;   // grid (2, 2, 7)
    gemm_core<false, false, 128, 256, 128, false>(
        g_cbz + m * K_ * D_, W1 + (m * 2) * H_ * D_, g_P1 + m * K_ * H_, nullptr);
}
__global__ void __launch_bounds__(256) k_yg(const float* __restrict__ Wc, int m, int ping) {
    gemm_core<false, false, 128, 128, 256, false>(
        ping ? g_xb : g_xa, Wc + m * D_ * 2 * D_ + D_, g_y, nullptr);       // grid (1, 8)
}
__global__ void __launch_bounds__(256) k_q1g(const float* __restrict__ W1, int m) {
    gemm_core<false, false, 128, 256, 128, false>(
        g_y, W1 + (m * 2) * H_ * D_, g_Q1, nullptr);                        // grid (2, 8)
}

// ---- fused layer-0 GEMM2: z = (cbz[k]+y[b]) + relu(P1[k]+Q1[b]) @ W2_0^T ----
__global__ void __launch_bounds__(256) k_gemm2_l0(const float* __restrict__ W2, int m) {
    constexpr int K = H_;   // 256
    constexpr int O = D_;   // 128
    __shared__ float As[2][8][128];
    __shared__ float Bs[2][8][128];
    const int tid  = threadIdx.x;
    const int cRow = blockIdx.y * 128;       // cCol = 0
    const int tRow = (tid >> 4) * 8;
    const int tCol = (tid & 15) * 8;
    const int rA = tid >> 1;
    const int cA = (tid & 1) * 4;

    const int rGlob = cRow + rA;
    const int bb = rGlob >> 8;
    const int kk_ = rGlob & 255;
    const float* Pp = g_P1 + (m * K_ + kk_) * H_ + cA;
    const float* Qp = g_Q1 + bb * H_ + cA;
    const float* Wp = W2 + rA * K + cA;

    uint64_t acc2[8][4] = {};

    float4 p = *(const float4*)Pp;
    float4 q = *(const float4*)Qp;
    float4 b4 = *(const float4*)Wp;
    float4 a4 = make_float4(fmaxf(p.x + q.x, 0.f), fmaxf(p.y + q.y, 0.f),
                            fmaxf(p.z + q.z, 0.f), fmaxf(p.w + q.w, 0.f));
    As[0][cA+0][rA]=a4.x; As[0][cA+1][rA]=a4.y; As[0][cA+2][rA]=a4.z; As[0][cA+3][rA]=a4.w;
    Bs[0][cA+0][rA]=b4.x; Bs[0][cA+1][rA]=b4.y; Bs[0][cA+2][rA]=b4.z; Bs[0][cA+3][rA]=b4.w;
    __syncthreads();

    constexpr int NT = K / 8;   // 32
    int buf = 0;
#pragma unroll 1
    for (int it = 0; it < NT; ++it) {
        float4 an, bn;
        if (it + 1 < NT) {
            float4 pn = *(const float4*)(Pp + (it + 1) * 8);
            float4 qn = *(const float4*)(Qp + (it + 1) * 8);
            an = make_float4(fmaxf(pn.x + qn.x, 0.f), fmaxf(pn.y + qn.y, 0.f),
                             fmaxf(pn.z + qn.z, 0.f), fmaxf(pn.w + qn.w, 0.f));
            bn = *(const float4*)(Wp + (it + 1) * 8);
        }
#pragma unroll
        for (int kk = 0; kk < 8; ++kk) {
            float rm[8];
            *(float4*)(rm)   = *(const float4*)&As[buf][kk][tRow];
            *(float4*)(rm+4) = *(const float4*)&As[buf][kk][tRow+4];
            uint64_t rn2[4];
            *(uint4*)(&rn2[0]) = *(const uint4*)&Bs[buf][kk][tCol];
            *(uint4*)(&rn2[2]) = *(const uint4*)&Bs[buf][kk][tCol+4];
#pragma unroll
            for (int i = 0; i < 8; ++i) {
                uint64_t am = dup2(rm[i]);
#pragma unroll
                for (int j = 0; j < 4; ++j) fma2(acc2[i][j], am, rn2[j]);
            }
        }
        if (it + 1 < NT) {
            int nb = buf ^ 1;
            As[nb][cA+0][rA]=an.x; As[nb][cA+1][rA]=an.y; As[nb][cA+2][rA]=an.z; As[nb][cA+3][rA]=an.w;
            Bs[nb][cA+0][rA]=bn.x; Bs[nb][cA+1][rA]=bn.y; Bs[nb][cA+2][rA]=bn.z; Bs[nb][cA+3][rA]=bn.w;
            __syncthreads();
            buf = nb;
        }
    }

    // epilogue: add base z0 = cbz[m][k] + y[b]
#pragma unroll
    for (int i = 0; i < 8; ++i) {
        float vv[8];
#pragma unroll
        for (int j = 0; j < 4; ++j) {
            float2 t = u2f(acc2[i][j]);
            vv[2*j] = t.x; vv[2*j+1] = t.y;
        }
        int r = cRow + tRow + i;
        int eb = r >> 8, ek = r & 255;
        const float* cbzr = g_cbz + (m * K_ + ek) * D_ + tCol;
        const float* yr   = g_y + eb * D_ + tCol;
        float* cp = g_z + r * O + tCol;
#pragma unroll
        for (int j4 = 0; j4 < 8; j4 += 4) {
            float4 c = *(const float4*)(cbzr + j4);
            float4 y = *(const float4*)(yr + j4);
            float4 v = make_float4(vv[j4] + c.x + y.x, vv[j4+1] + c.y + y.y,
                                   vv[j4+2] + c.z + y.z, vv[j4+3] + c.w + y.w);
            *(float4*)(cp + j4) = v;
        }
    }
}

// ---- step 0: argmin_k |x - cb0[k]|^2 ----
__global__ void k_step0(const float* __restrict__ x, const float* __restrict__ cb0,
                        float* __restrict__ out) {
    int b = blockIdx.x, t = threadIdx.x;
    int w = t >> 5, lane = t & 31;
    __shared__ float4 xs[32];
    __shared__ float  sd[256];
    __shared__ int    si[256];
    if (t < 32) xs[t] = ((const float4*)x)[b * 32 + t];
    __syncthreads();
    float4 xv = xs[lane];
    for (int i = 0; i < 32; ++i) {
        int k = w * 32 + i;
        float4 c = ((const float4*)cb0)[k * 32 + lane];
        float a1 = c.x*c.x + c.y*c.y + c.z*c.z + c.w*c.w;
        float a2 = xv.x*c.x + xv.y*c.y + xv.z*c.z + xv.w*c.w;
        warp_red2(a1, a2);
        if (lane == 0) sd[k] = a1 - 2.f * a2;
    }
    si[t] = t;
    __syncthreads();
    for (int s = 128; s; s >>= 1) {
        if (t < s) {
            float o = sd[t + s]; int oi = si[t + s];
            if (o < sd[t] || (o == sd[t] && oi < si[t])) { sd[t] = o; si[t] = oi; }
        }
        __syncthreads();
    }
    int kb = si[0];
    if (t < D_) {
        float v = cb0[kb * D_ + t];
        g_xa[b * D_ + t] = v;
        out[OUT_SIDE + b * D_ + t] = v;       // side[0]
    }
    if (t == 0) out[OUT_CODES + b * M_] = (float)kb;
}

// ---- step m: zf = z + xhat; argmin; update xhat; emit outputs ----
__global__ void k_argupd(const float* __restrict__ x, float* __restrict__ out,
                         int m, int ping) {
    const float* xin  = ping ? g_xb : g_xa;
    float*       xout = ping ? g_xa : g_xb;
    int b = blockIdx.x, t = threadIdx.x;
    int w = t >> 5, lane = t & 31;
    __shared__ float4 xs[32], hs[32];
    __shared__ float  sd[256];
    __shared__ int    si[256];
    if (t < 32) {
        xs[t] = ((const float4*)x)[b * 32 + t];
        hs[t] = ((const float4*)xin)[b * 32 + t];
    }
    __syncthreads();
    float4 xv = xs[lane], hv = hs[lane];
    const float4* zr = (const float4*)g_z + b * (K_ * 32);
    for (int i = 0; i < 32; ++i) {
        int k = w * 32 + i;
        float4 z = zr[k * 32 + lane];
        z.x += hv.x; z.y += hv.y; z.z += hv.z; z.w += hv.w;
        float a1 = z.x*z.x + z.y*z.y + z.z*z.z + z.w*z.w;
        float a2 = xv.x*z.x + xv.y*z.y + xv.z*z.z + xv.w*z.w;
        warp_red2(a1, a2);
        if (lane == 0) sd[k] = a1 - 2.f * a2;
    }
    si[t] = t;
    __syncthreads();
    for (int s = 128; s; s >>= 1) {
        if (t < s) {
            float o = sd[t + s]; int oi = si[t + s];
            if (o < sd[t] || (o == sd[t] && oi < si[t])) { sd[t] = o; si[t] = oi; }
        }
        __syncthreads();
    }
    int kb = si[0];
    if (t < D_) {
        float v = g_z[(b * K_ + kb) * D_ + t] + xin[b * D_ + t];
        xout[b * D_ + t] = v;
        out[OUT_SIDE + (m + 1) * SIDE_SZ + b * D_ + t] = v;
        if (m == M_ - 2) out[b * D_ + t] = v;
    }
    if (t == 0) out[OUT_CODES + b * M_ + m + 1] = (float)kb;
}

extern "C" void kernel_launch(void* const* d_in, const int* in_sizes, int n_in,
                              void* d_out, int out_size) {
    const float* x   = (const float*)d_in[0];
    const float* cb0 = (const float*)d_in[1];
    const float* cbs = (const float*)d_in[2];
    const float* Wc  = (const float*)d_in[3];
    const float* bc  = (const float*)d_in[4];
    const float* W1  = (const float*)d_in[5];
    const float* W2  = (const float*)d_in[6];
    float* out = (float*)d_out;

    // weight-only precomputes (coalesced GEMM form)
    k_cbzg<<<dim3(1, 2, 7), 256>>>(cbs, Wc, bc);
    k_p1g<<<dim3(2, 2, 7), 256>>>(W1);
    k_step0<<<BS_, 256>>>(x, cb0, out);

    int ping = 0;   // xhat currently in g_xa
    for (int m = 0; m < M_ - 1; ++m) {
        k_yg<<<dim3(1, 8), 256>>>(Wc, m, ping);
        k_q1g<<<dim3(2, 8), 256>>>(W1, m);
        // layer 0 (GEMM1 eliminated algebraically; base + h0 fused)
        k_gemm2_l0<<<dim3(1, NR / 128), 256>>>(W2 + (m * 2) * D_ * H_, m);
        // layer 1 (full GEMMs)
        k_gemm1<<<dim3(H_ / 128, NR / 128), 256>>>(W1 + (m * 2 + 1) * H_ * D_);
        k_gemm2<<<dim3(D_ / 128, NR / 128), 256>>>(W2 + (m * 2 + 1) * D_ * H_);
        k_argupd<<<BS_, 256>>>(x, out, m, ping);
        ping ^= 1;
    }
}

// round 6
// speedup vs baseline: 1.2927x; 1.1708x over previous
#include <cuda_runtime.h>
#include <cuda_bf16.h>
#include <stdint.h>

// QINCo: D=128, M=8, K=256, L=2, H=256, BS=1024
namespace {
constexpr int D_  = 128;
constexpr int K_  = 256;
constexpr int M_  = 8;
constexpr int H_  = 256;
constexpr int BS_ = 1024;
constexpr int NR  = BS_ * K_;                   // 262144

constexpr int OUT_CODES = BS_ * D_;             // 131072
constexpr int OUT_SIDE  = OUT_CODES + BS_ * M_; // 139264
constexpr int SIDE_SZ   = BS_ * D_;

constexpr int LIMB  = 10240;                    // 128 rows * 80B (padded, ldmatrix-conflict-free)
constexpr int SBOFF = 3 * LIMB;
constexpr int STG   = 6 * LIMB;                 // one stage: A(3 limbs) + B(3 limbs)
constexpr int SMEM_MMA = 2 * STG;               // 122880 B, double buffered
}

// ---- device scratch (allocation-free) ----
__device__ __align__(128) float g_z[NR * D_];
__device__ __align__(128) float g_h[NR * H_];
__device__ __align__(128) float g_cbz[(M_-1) * K_ * D_];
__device__ __align__(128) float g_P1[(M_-1) * K_ * H_];
__device__ __align__(128) float g_y[BS_ * D_];
__device__ __align__(128) float g_Q1[BS_ * H_];
__device__ __align__(128) float g_xa[BS_ * D_];
__device__ __align__(128) float g_xb[BS_ * D_];
// weight limbs: W1 layer-1 [7][256][128]; W2 both layers [14][128][256]
__device__ __align__(128) __nv_bfloat16 g_w1a[7*32768], g_w1b[7*32768], g_w1c[7*32768];
__device__ __align__(128) __nv_bfloat16 g_w2a[14*32768], g_w2b[14*32768], g_w2c[14*32768];

// ================= helpers =================
__device__ __forceinline__ uint32_t smem_u32(const void* p) {
    uint32_t a;
    asm("{ .reg .u64 t; cvta.to.shared.u64 t, %1; cvt.u32.u64 %0, t; }" : "=r"(a) : "l"(p));
    return a;
}
__device__ __forceinline__ void split3(float a, __nv_bfloat16& h, __nv_bfloat16& m, __nv_bfloat16& l) {
    h = __float2bfloat16(a); float r = a - __bfloat162float(h);
    m = __float2bfloat16(r); r -= __bfloat162float(m);
    l = __float2bfloat16(r);
}
__device__ __forceinline__ uint32_t pk(__nv_bfloat16 a, __nv_bfloat16 b) {
    return (uint32_t)__bfloat16_as_ushort(a) | ((uint32_t)__bfloat16_as_ushort(b) << 16);
}
__device__ __forceinline__ void warp_red2(float& a, float& b) {
#pragma unroll
    for (int o = 16; o; o >>= 1) {
        a += __shfl_xor_sync(0xffffffffu, a, o);
        b += __shfl_xor_sync(0xffffffffu, b, o);
    }
}
__device__ __forceinline__ void mma_bf16(float* c, const uint32_t* a, const uint32_t* b) {
    asm volatile("mma.sync.aligned.m16n8k16.row.col.f32.bf16.bf16.f32 "
        "{%0,%1,%2,%3}, {%4,%5,%6,%7}, {%8,%9}, {%0,%1,%2,%3};"
        : "+f"(c[0]), "+f"(c[1]), "+f"(c[2]), "+f"(c[3])
        : "r"(a[0]), "r"(a[1]), "r"(a[2]), "r"(a[3]), "r"(b[0]), "r"(b[1]));
}
__device__ __forceinline__ void ldm4(uint32_t* r, uint32_t addr) {
    asm volatile("ldmatrix.sync.aligned.m8n8.x4.shared.b16 {%0,%1,%2,%3}, [%4];"
        : "=r"(r[0]), "=r"(r[1]), "=r"(r[2]), "=r"(r[3]) : "r"(addr));
}
__device__ __forceinline__ void cpasync16(uint32_t s, const void* g) {
    asm volatile("cp.async.cg.shared.global [%0], [%1], 16;" :: "r"(s), "l"(g));
}
// packed fp32 (for small GEMMs)
__device__ __forceinline__ uint64_t dup2(float x) {
    uint64_t r; asm("mov.b64 %0, {%1, %1};" : "=l"(r) : "f"(x)); return r;
}
__device__ __forceinline__ void fma2(uint64_t& d, uint64_t a, uint64_t b) {
    asm("fma.rn.f32x2 %0, %1, %2, %0;" : "+l"(d) : "l"(a), "l"(b));
}
__device__ __forceinline__ float2 u2f(uint64_t v) {
    float2 r; asm("mov.b64 {%0, %1}, %2;" : "=f"(r.x), "=f"(r.y) : "l"(v)); return r;
}

// ================= weight limb split (once per launch) =================
__global__ void k_splitw(const float* __restrict__ W1, const float* __restrict__ W2) {
    int i = blockIdx.x * 256 + threadIdx.x;
    if (i < 7 * 32768) {     // W1 layer-1 slices
        int mm = i / 32768, r = i % 32768;
        __nv_bfloat16 h, m, l;
        split3(W1[(mm * 2 + 1) * 32768 + r], h, m, l);
        g_w1a[i] = h; g_w1b[i] = m; g_w1c[i] = l;
    }
    if (i < 14 * 32768) {    // all W2
        __nv_bfloat16 h, m, l;
        split3(W2[i], h, m, l);
        g_w2a[i] = h; g_w2b[i] = m; g_w2c[i] = l;
    }
}

// ================= tensor-core GEMM: bf16 3-limb / 6-pass mma.sync =================
// MODE 0: z[(b,k),:] = (cbz[k]+y[b]) + relu(P1[k]+Q1[b]) @ W2_0^T   K=256, grid (1,2048)
// MODE 1: h = relu(z @ W1_1^T)                                       K=128, grid (2,2048)
// MODE 2: z += h @ W2_1^T                                            K=256, grid (1,2048)
template <int MODE>
__global__ void __launch_bounds__(256, 1) k_mma(int m) {
    constexpr int KDIM = (MODE == 1) ? 128 : 256;
    constexpr int NS = KDIM / 32;
    extern __shared__ char sm[];
    uint32_t sb = smem_u32(sm);
    const int tid = threadIdx.x, lane = tid & 31, wid = tid >> 5;
    const int cRow = blockIdx.y * 128, cCol = blockIdx.x * 128;
    const int wr = (wid >> 2) * 64, wc = (wid & 3) * 32;

    const __nv_bfloat16 *B0, *B1, *B2;
    if (MODE == 1) {
        B0 = g_w1a + m*32768; B1 = g_w1b + m*32768; B2 = g_w1c + m*32768;
    } else {
        int sl = (MODE == 0) ? 2*m : 2*m + 1;
        B0 = g_w2a + sl*32768; B1 = g_w2b + sl*32768; B2 = g_w2c + sl*32768;
    }

    float acc[4][4][4] = {};
    float ar[16];

    // ---- A-tile global load into regs (fp32 source) ----
    auto ldgA = [&](int kc) {
#pragma unroll
        for (int i = 0; i < 4; ++i) {
            int idx = tid + 256*i, row = idx >> 3, q = idx & 7;
            int rg = cRow + row;
            float4 v;
            if (MODE == 0) {
                int k = rg & 255, b = rg >> 8;
                float4 p = *(const float4*)(g_P1 + (m*K_ + k)*H_ + kc + q*4);
                float4 qq = *(const float4*)(g_Q1 + b*H_ + kc + q*4);
                v = make_float4(fmaxf(p.x+qq.x, 0.f), fmaxf(p.y+qq.y, 0.f),
                                fmaxf(p.z+qq.z, 0.f), fmaxf(p.w+qq.w, 0.f));
            } else if (MODE == 1) {
                v = *(const float4*)(g_z + rg*128 + kc + q*4);
            } else {
                v = *(const float4*)(g_h + rg*256 + kc + q*4);
            }
            ar[i*4+0] = v.x; ar[i*4+1] = v.y; ar[i*4+2] = v.z; ar[i*4+3] = v.w;
        }
    };
    // ---- split regs -> smem limb tiles ----
    auto stsA = [&](int buf) {
#pragma unroll
        for (int i = 0; i < 4; ++i) {
            int idx = tid + 256*i, row = idx >> 3, q = idx & 7;
            __nv_bfloat16 hh[4], mm2[4], ll[4];
#pragma unroll
            for (int j = 0; j < 4; ++j) split3(ar[i*4+j], hh[j], mm2[j], ll[j]);
            char* base = sm + buf*STG + row*80 + q*8;
            *(uint2*)(base + 0*LIMB) = make_uint2(pk(hh[0],hh[1]),  pk(hh[2],hh[3]));
            *(uint2*)(base + 1*LIMB) = make_uint2(pk(mm2[0],mm2[1]), pk(mm2[2],mm2[3]));
            *(uint2*)(base + 2*LIMB) = make_uint2(pk(ll[0],ll[1]),  pk(ll[2],ll[3]));
        }
    };
    // ---- B limbs via cp.async ----
    auto cpB = [&](int buf, int kc) {
#pragma unroll
        for (int limb = 0; limb < 3; ++limb) {
            const __nv_bfloat16* Bp = (limb == 0) ? B0 : (limb == 1) ? B1 : B2;
#pragma unroll
            for (int i = 0; i < 2; ++i) {
                int r2 = tid + 256*i, row = r2 >> 2, cq = r2 & 3;
                uint32_t dst = sb + buf*STG + SBOFF + limb*LIMB + row*80 + cq*16;
                cpasync16(dst, Bp + (cCol + row)*KDIM + kc + cq*8);
            }
        }
    };
    // ---- compute one 32-wide k stage ----
    auto compute = [&](int buf) {
#pragma unroll
        for (int h16 = 0; h16 < 2; ++h16) {
            const int kb = h16 * 32;
            uint32_t aF[3][4][4], bF[3][4][2];
#pragma unroll
            for (int limb = 0; limb < 3; ++limb) {
#pragma unroll
                for (int mt = 0; mt < 4; ++mt) {
                    int row = wr + mt*16 + (lane & 7) + ((lane >> 3) & 1)*8;
                    int boff = kb + (lane >> 4)*16;
                    ldm4(aF[limb][mt], sb + buf*STG + limb*LIMB + row*80 + boff);
                }
#pragma unroll
                for (int p = 0; p < 2; ++p) {
                    int row = wc + p*16 + (lane & 7) + ((lane >> 4) & 1)*8;
                    int boff = kb + ((lane >> 3) & 1)*16;
                    uint32_t r[4];
                    ldm4(r, sb + buf*STG + SBOFF + limb*LIMB + row*80 + boff);
                    bF[limb][p*2  ][0] = r[0]; bF[limb][p*2  ][1] = r[1];
                    bF[limb][p*2+1][0] = r[2]; bF[limb][p*2+1][1] = r[3];
                }
            }
            const int la[6] = {0,0,1,1,0,2};
            const int lb[6] = {0,1,0,1,2,0};
#pragma unroll
            for (int p = 0; p < 6; ++p)
#pragma unroll
                for (int mt = 0; mt < 4; ++mt)
#pragma unroll
                    for (int nt = 0; nt < 4; ++nt)
                        mma_bf16(acc[mt][nt], aF[la[p]][mt], bF[lb[p]][nt]);
        }
    };

    // ---- pipeline ----
    ldgA(0);
    cpB(0, 0);
    asm volatile("cp.async.commit_group;" ::: "memory");
    stsA(0);
    asm volatile("cp.async.wait_group 0;" ::: "memory");
    __syncthreads();
    int buf = 0;
#pragma unroll 1
    for (int s = 0; s < NS; ++s) {
        if (s + 1 < NS) {
            ldgA((s+1) * 32);
            cpB(buf ^ 1, (s+1) * 32);
            asm volatile("cp.async.commit_group;" ::: "memory");
        }
        compute(buf);
        if (s + 1 < NS) {
            stsA(buf ^ 1);
            asm volatile("cp.async.wait_group 0;" ::: "memory");
            __syncthreads();
            buf ^= 1;
        }
    }

    // ---- epilogue ----
    const int g4 = lane >> 2, q2 = (lane & 3) * 2;
#pragma unroll
    for (int mt = 0; mt < 4; ++mt) {
#pragma unroll
        for (int nt = 0; nt < 4; ++nt) {
#pragma unroll
            for (int half = 0; half < 2; ++half) {
                int rg = cRow + wr + mt*16 + g4 + half*8;
                int c  = cCol + wc + nt*8 + q2;
                float v0 = acc[mt][nt][half*2], v1 = acc[mt][nt][half*2 + 1];
                if (MODE == 0) {
                    int b = rg >> 8, k = rg & 255;
                    const float* cz = g_cbz + (m*K_ + k)*D_ + c;
                    const float* yy = g_y + b*D_ + c;
                    v0 += cz[0] + yy[0]; v1 += cz[1] + yy[1];
                    *(float2*)(g_z + rg*D_ + c) = make_float2(v0, v1);
                } else if (MODE == 1) {
                    v0 = fmaxf(v0, 0.f); v1 = fmaxf(v1, 0.f);
                    *(float2*)(g_h + rg*H_ + c) = make_float2(v0, v1);
                } else {
                    float2 z = *(float2*)(g_z + rg*D_ + c);
                    *(float2*)(g_z + rg*D_ + c) = make_float2(z.x + v0, z.y + v1);
                }
            }
        }
    }
}

// ================= f32x2 mini-GEMM core (small per-step / precompute GEMMs) =================
template <bool RELU, bool ACC, int K, int O, int WS, bool EPIAB>
__device__ __forceinline__ void gemm_core(const float* __restrict__ A,
                                          const float* __restrict__ W,
                                          float* __restrict__ C,
                                          const float* __restrict__ bias) {
    __shared__ float As[2][8][128];
    __shared__ float Bs[2][8][128];
    const int tid  = threadIdx.x;
    const int cRow = blockIdx.y * 128;
    const int cCol = blockIdx.x * 128;
    const int tRow = (tid >> 4) * 8;
    const int tCol = (tid & 15) * 8;
    const int rA = tid >> 1;
    const int cA = (tid & 1) * 4;

    uint64_t acc2[8][4] = {};
    const float* Ap = A + (cRow + rA) * K + cA;
    const float* Wp = W + (cCol + rA) * WS + cA;

    float4 a4 = *(const float4*)Ap;
    float4 b4 = *(const float4*)Wp;
    As[0][cA+0][rA]=a4.x; As[0][cA+1][rA]=a4.y; As[0][cA+2][rA]=a4.z; As[0][cA+3][rA]=a4.w;
    Bs[0][cA+0][rA]=b4.x; Bs[0][cA+1][rA]=b4.y; Bs[0][cA+2][rA]=b4.z; Bs[0][cA+3][rA]=b4.w;
    __syncthreads();

    constexpr int NT = K / 8;
    int buf = 0;
#pragma unroll 1
    for (int it = 0; it < NT; ++it) {
        float4 an, bn;
        if (it + 1 < NT) {
            an = *(const float4*)(Ap + (it + 1) * 8);
            bn = *(const float4*)(Wp + (it + 1) * 8);
        }
#pragma unroll
        for (int kk = 0; kk < 8; ++kk) {
            float rm[8];
            *(float4*)(rm)   = *(const float4*)&As[buf][kk][tRow];
            *(float4*)(rm+4) = *(const float4*)&As[buf][kk][tRow+4];
            uint64_t rn2[4];
            *(uint4*)(&rn2[0]) = *(const uint4*)&Bs[buf][kk][tCol];
            *(uint4*)(&rn2[2]) = *(const uint4*)&Bs[buf][kk][tCol+4];
#pragma unroll
            for (int i = 0; i < 8; ++i) {
                uint64_t am = dup2(rm[i]);
#pragma unroll
                for (int j = 0; j < 4; ++j) fma2(acc2[i][j], am, rn2[j]);
            }
        }
        if (it + 1 < NT) {
            int nb = buf ^ 1;
            As[nb][cA+0][rA]=an.x; As[nb][cA+1][rA]=an.y; As[nb][cA+2][rA]=an.z; As[nb][cA+3][rA]=an.w;
            Bs[nb][cA+0][rA]=bn.x; Bs[nb][cA+1][rA]=bn.y; Bs[nb][cA+2][rA]=bn.z; Bs[nb][cA+3][rA]=bn.w;
            __syncthreads();
            buf = nb;
        }
    }
#pragma unroll
    for (int i = 0; i < 8; ++i) {
        float vv[8];
#pragma unroll
        for (int j = 0; j < 4; ++j) {
            float2 t = u2f(acc2[i][j]);
            vv[2*j] = t.x; vv[2*j+1] = t.y;
        }
        float* cp = C + (cRow + tRow + i) * O + cCol + tCol;
#pragma unroll
        for (int j4 = 0; j4 < 8; j4 += 4) {
            float4 v = make_float4(vv[j4], vv[j4+1], vv[j4+2], vv[j4+3]);
            if (ACC) {
                float4 o = *(const float4*)(cp + j4);
                v.x += o.x; v.y += o.y; v.z += o.z; v.w += o.w;
            }
            if (EPIAB) {
                float4 av = *(const float4*)(A + (cRow + tRow + i) * K + cCol + tCol + j4);
                float4 bb = *(const float4*)(bias + cCol + tCol + j4);
                v.x += av.x + bb.x; v.y += av.y + bb.y;
                v.z += av.z + bb.z; v.w += av.w + bb.w;
            }
            if (RELU) {
                v.x = fmaxf(v.x, 0.f); v.y = fmaxf(v.y, 0.f);
                v.z = fmaxf(v.z, 0.f); v.w = fmaxf(v.w, 0.f);
            }
            *(float4*)(cp + j4) = v;
        }
    }
}

__global__ void __launch_bounds__(256) k_cbzg(const float* __restrict__ cbs,
                                              const float* __restrict__ Wc,
                                              const float* __restrict__ bc) {
    int m = blockIdx.z;   // grid (1, 2, 7)
    gemm_core<false, false, 128, 128, 256, true>(
        cbs + m * K_ * D_, Wc + m * D_ * 2 * D_, g_cbz + m * K_ * D_, bc + m * D_);
}
__global__ void __launch_bounds__(256) k_p1g(const float* __restrict__ W1) {
    int m = blockIdx.z;   // grid (2, 2, 7)
    gemm_core<false, false, 128, 256, 128, false>(
        g_cbz + m * K_ * D_, W1 + (m * 2) * H_ * D_, g_P1 + m * K_ * H_, nullptr);
}
__global__ void __launch_bounds__(256) k_yg(const float* __restrict__ Wc, int m, int ping) {
    gemm_core<false, false, 128, 128, 256, false>(
        ping ? g_xb : g_xa, Wc + m * D_ * 2 * D_ + D_, g_y, nullptr);       // grid (1, 8)
}
__global__ void __launch_bounds__(256) k_q1g(const float* __restrict__ W1, int m) {
    gemm_core<false, false, 128, 256, 128, false>(
        g_y, W1 + (m * 2) * H_ * D_, g_Q1, nullptr);                        // grid (2, 8)
}

// ================= argmin kernels (fp32) =================
__global__ void k_step0(const float* __restrict__ x, const float* __restrict__ cb0,
                        float* __restrict__ out) {
    int b = blockIdx.x, t = threadIdx.x;
    int w = t >> 5, lane = t & 31;
    __shared__ float4 xs[32];
    __shared__ float  sd[256];
    __shared__ int    si[256];
    if (t < 32) xs[t] = ((const float4*)x)[b * 32 + t];
    __syncthreads();
    float4 xv = xs[lane];
    for (int i = 0; i < 32; ++i) {
        int k = w * 32 + i;
        float4 c = ((const float4*)cb0)[k * 32 + lane];
        float a1 = c.x*c.x + c.y*c.y + c.z*c.z + c.w*c.w;
        float a2 = xv.x*c.x + xv.y*c.y + xv.z*c.z + xv.w*c.w;
        warp_red2(a1, a2);
        if (lane == 0) sd[k] = a1 - 2.f * a2;
    }
    si[t] = t;
    __syncthreads();
    for (int s = 128; s; s >>= 1) {
        if (t < s) {
            float o = sd[t + s]; int oi = si[t + s];
            if (o < sd[t] || (o == sd[t] && oi < si[t])) { sd[t] = o; si[t] = oi; }
        }
        __syncthreads();
    }
    int kb = si[0];
    if (t < D_) {
        float v = cb0[kb * D_ + t];
        g_xa[b * D_ + t] = v;
        out[OUT_SIDE + b * D_ + t] = v;       // side[0]
    }
    if (t == 0) out[OUT_CODES + b * M_] = (float)kb;
}

__global__ void k_argupd(const float* __restrict__ x, float* __restrict__ out,
                         int m, int ping) {
    const float* xin  = ping ? g_xb : g_xa;
    float*       xout = ping ? g_xa : g_xb;
    int b = blockIdx.x, t = threadIdx.x;
    int w = t >> 5, lane = t & 31;
    __shared__ float4 xs[32], hs[32];
    __shared__ float  sd[256];
    __shared__ int    si[256];
    if (t < 32) {
        xs[t] = ((const float4*)x)[b * 32 + t];
        hs[t] = ((const float4*)xin)[b * 32 + t];
    }
    __syncthreads();
    float4 xv = xs[lane], hv = hs[lane];
    const float4* zr = (const float4*)g_z + b * (K_ * 32);
    for (int i = 0; i < 32; ++i) {
        int k = w * 32 + i;
        float4 z = zr[k * 32 + lane];
        z.x += hv.x; z.y += hv.y; z.z += hv.z; z.w += hv.w;
        float a1 = z.x*z.x + z.y*z.y + z.z*z.z + z.w*z.w;
        float a2 = xv.x*z.x + xv.y*z.y + xv.z*z.z + xv.w*z.w;
        warp_red2(a1, a2);
        if (lane == 0) sd[k] = a1 - 2.f * a2;
    }
    si[t] = t;
    __syncthreads();
    for (int s = 128; s; s >>= 1) {
        if (t < s) {
            float o = sd[t + s]; int oi = si[t + s];
            if (o < sd[t] || (o == sd[t] && oi < si[t])) { sd[t] = o; si[t] = oi; }
        }
        __syncthreads();
    }
    int kb = si[0];
    if (t < D_) {
        float v = g_z[(b * K_ + kb) * D_ + t] + xin[b * D_ + t];
        xout[b * D_ + t] = v;
        out[OUT_SIDE + (m + 1) * SIDE_SZ + b * D_ + t] = v;
        if (m == M_ - 2) out[b * D_ + t] = v;
    }
    if (t == 0) out[OUT_CODES + b * M_ + m + 1] = (float)kb;
}

extern "C" void kernel_launch(void* const* d_in, const int* in_sizes, int n_in,
                              void* d_out, int out_size) {
    const float* x   = (const float*)d_in[0];
    const float* cb0 = (const float*)d_in[1];
    const float* cbs = (const float*)d_in[2];
    const float* Wc  = (const float*)d_in[3];
    const float* bc  = (const float*)d_in[4];
    const float* W1  = (const float*)d_in[5];
    const float* W2  = (const float*)d_in[6];
    float* out = (float*)d_out;

    cudaFuncSetAttribute(k_mma<0>, cudaFuncAttributeMaxDynamicSharedMemorySize, SMEM_MMA);
    cudaFuncSetAttribute(k_mma<1>, cudaFuncAttributeMaxDynamicSharedMemorySize, SMEM_MMA);
    cudaFuncSetAttribute(k_mma<2>, cudaFuncAttributeMaxDynamicSharedMemorySize, SMEM_MMA);

    // weight-only precomputes
    k_splitw<<<1792, 256>>>(W1, W2);
    k_cbzg<<<dim3(1, 2, 7), 256>>>(cbs, Wc, bc);
    k_p1g<<<dim3(2, 2, 7), 256>>>(W1);
    k_step0<<<BS_, 256>>>(x, cb0, out);

    int ping = 0;   // xhat currently in g_xa
    for (int m = 0; m < M_ - 1; ++m) {
        k_yg<<<dim3(1, 8), 256>>>(Wc, m, ping);
        k_q1g<<<dim3(2, 8), 256>>>(W1, m);
        k_mma<0><<<dim3(1, NR / 128), 256, SMEM_MMA>>>(m);   // layer0 fused
        k_mma<1><<<dim3(2, NR / 128), 256, SMEM_MMA>>>(m);   // h = relu(z @ W1^T)
        k_mma<2><<<dim3(1, NR / 128), 256, SMEM_MMA>>>(m);   // z += h @ W2^T
        k_argupd<<<BS_, 256>>>(x, out, m, ping);
        ping ^= 1;
    }
}

// round 8
// speedup vs baseline: 1.4643x; 1.1328x over previous
#include <cuda_runtime.h>
#include <cuda_fp16.h>
#include <stdint.h>

// QINCo: D=128, M=8, K=256, L=2, H=256, BS=1024
namespace {
constexpr int D_  = 128;
constexpr int K_  = 256;
constexpr int M_  = 8;
constexpr int H_  = 256;
constexpr int BS_ = 1024;
constexpr int NR  = BS_ * K_;                   // 262144

constexpr int OUT_CODES = BS_ * D_;             // 131072
constexpr int OUT_SIDE  = OUT_CODES + BS_ * M_; // 139264
constexpr int SIDE_SZ   = BS_ * D_;

constexpr int LIMB  = 10240;                    // 128 rows * 80B (padded)
constexpr int SBOFF = 2 * LIMB;
constexpr int STG   = 4 * LIMB;                 // stage: A(2 limbs) + B(2 limbs)
constexpr int SMEM_MMA = 2 * STG;               // 81920 B, double buffered
constexpr float TAU = 1e-2f;                    // rescue threshold on dist
}

// ---- device scratch (allocation-free) ----
__device__ __align__(128) float g_z[NR * D_];
__device__ __align__(128) float g_h[NR * H_];
__device__ __align__(128) float g_cbz[(M_-1) * K_ * D_];
__device__ __align__(128) float g_P1[(M_-1) * K_ * H_];
__device__ __align__(128) float g_y[BS_ * D_];
__device__ __align__(128) float g_Q1[BS_ * H_];
__device__ __align__(128) float g_xa[BS_ * D_];
__device__ __align__(128) float g_xb[BS_ * D_];
// fp16 2-limb weights: W1 layer-1 [7][256][128]; W2 both layers [14][128][256]
__device__ __align__(128) __half g_w1a[7*32768], g_w1b[7*32768];
__device__ __align__(128) __half g_w2a[14*32768], g_w2b[14*32768];
// winner / rescue machinery
__device__ __align__(128) float g_h0w[BS_ * H_];
__device__ __align__(128) float g_z1w[BS_ * D_];
__device__ __align__(128) float g_h1w[BS_ * H_];
__device__ int g_code[BS_];
__device__ int g_ccount[BS_];
__device__ int g_clist[BS_ * 16];

// ================= helpers =================
__device__ __forceinline__ uint32_t smem_u32(const void* p) {
    uint32_t a;
    asm("{ .reg .u64 t; cvta.to.shared.u64 t, %1; cvt.u32.u64 %0, t; }" : "=r"(a) : "l"(p));
    return a;
}
__device__ __forceinline__ void split2(float a, __half& h, __half& l) {
    h = __float2half_rn(a);
    l = __float2half_rn((a - __half2float(h)) * 2048.0f);
}
__device__ __forceinline__ uint32_t pkh(__half a, __half b) {
    return (uint32_t)__half_as_ushort(a) | ((uint32_t)__half_as_ushort(b) << 16);
}
__device__ __forceinline__ void warp_red2(float& a, float& b) {
#pragma unroll
    for (int o = 16; o; o >>= 1) {
        a += __shfl_xor_sync(0xffffffffu, a, o);
        b += __shfl_xor_sync(0xffffffffu, b, o);
    }
}
__device__ __forceinline__ void mma_f16(float* c, const uint32_t* a, const uint32_t* b) {
    asm volatile("mma.sync.aligned.m16n8k16.row.col.f32.f16.f16.f32 "
        "{%0,%1,%2,%3}, {%4,%5,%6,%7}, {%8,%9}, {%0,%1,%2,%3};"
        : "+f"(c[0]), "+f"(c[1]), "+f"(c[2]), "+f"(c[3])
        : "r"(a[0]), "r"(a[1]), "r"(a[2]), "r"(a[3]), "r"(b[0]), "r"(b[1]));
}
__device__ __forceinline__ void ldm4(uint32_t* r, uint32_t addr) {
    asm volatile("ldmatrix.sync.aligned.m8n8.x4.shared.b16 {%0,%1,%2,%3}, [%4];"
        : "=r"(r[0]), "=r"(r[1]), "=r"(r[2]), "=r"(r[3]) : "r"(addr));
}
__device__ __forceinline__ void cpasync16(uint32_t s, const void* g) {
    asm volatile("cp.async.cg.shared.global [%0], [%1], 16;" :: "r"(s), "l"(g));
}
// packed fp32 (for small exact GEMMs)
__device__ __forceinline__ uint64_t dup2(float x) {
    uint64_t r; asm("mov.b64 %0, {%1, %1};" : "=l"(r) : "f"(x)); return r;
}
__device__ __forceinline__ void fma2(uint64_t& d, uint64_t a, uint64_t b) {
    asm("fma.rn.f32x2 %0, %1, %2, %0;" : "+l"(d) : "l"(a), "l"(b));
}
__device__ __forceinline__ float2 u2f(uint64_t v) {
    float2 r; asm("mov.b64 {%0, %1}, %2;" : "=f"(r.x), "=f"(r.y) : "l"(v)); return r;
}

// ================= weight limb split (once per launch) =================
__global__ void k_splitw(const float* __restrict__ W1, const float* __restrict__ W2) {
    int i = blockIdx.x * 256 + threadIdx.x;
    if (i < 7 * 32768) {
        int mm = i / 32768, r = i % 32768;
        __half h, l;
        split2(W1[(mm * 2 + 1) * 32768 + r], h, l);
        g_w1a[i] = h; g_w1b[i] = l;
    }
    if (i < 14 * 32768) {
        __half h, l;
        split2(W2[i], h, l);
        g_w2a[i] = h; g_w2b[i] = l;
    }
}

// ================= tensor GEMM: fp16 2-limb / 3-pass mma.sync =================
// MODE 0: z[(b,k),:] = (cbz[k]+y[b]) + relu(P1[k]+Q1[b]) @ W2_0^T   K=256, grid (1,2048)
// MODE 1: h = relu(z @ W1_1^T)                                       K=128, grid (2,2048)
// MODE 2: z += h @ W2_1^T                                            K=256, grid (1,2048)
template <int MODE>
__global__ void __launch_bounds__(256, 1) k_mma(int m) {
    constexpr int KDIM = (MODE == 1) ? 128 : 256;
    constexpr int NS = KDIM / 32;
    extern __shared__ char sm[];
    uint32_t sb = smem_u32(sm);
    const int tid = threadIdx.x, lane = tid & 31, wid = tid >> 5;
    const int cRow = blockIdx.y * 128, cCol = blockIdx.x * 128;
    const int wr = (wid >> 2) * 64, wc = (wid & 3) * 32;

    const __half *B0, *B1;
    if (MODE == 1) {
        B0 = g_w1a + m*32768; B1 = g_w1b + m*32768;
    } else {
        int sl = (MODE == 0) ? 2*m : 2*m + 1;
        B0 = g_w2a + sl*32768; B1 = g_w2b + sl*32768;
    }

    float acc0[4][4][4] = {};
    float acc1[4][4][4] = {};
    float ar[16];

    auto ldgA = [&](int kc) {
#pragma unroll
        for (int i = 0; i < 4; ++i) {
            int idx = tid + 256*i, row = idx >> 3, q = idx & 7;
            int rg = cRow + row;
            float4 v;
            if (MODE == 0) {
                int k = rg & 255, b = rg >> 8;
                float4 p = *(const float4*)(g_P1 + (m*K_ + k)*H_ + kc + q*4);
                float4 qq = *(const float4*)(g_Q1 + b*H_ + kc + q*4);
                v = make_float4(fmaxf(p.x+qq.x, 0.f), fmaxf(p.y+qq.y, 0.f),
                                fmaxf(p.z+qq.z, 0.f), fmaxf(p.w+qq.w, 0.f));
            } else if (MODE == 1) {
                v = *(const float4*)(g_z + rg*128 + kc + q*4);
            } else {
                v = *(const float4*)(g_h + rg*256 + kc + q*4);
            }
            ar[i*4+0] = v.x; ar[i*4+1] = v.y; ar[i*4+2] = v.z; ar[i*4+3] = v.w;
        }
    };
    auto stsA = [&](int buf) {
#pragma unroll
        for (int i = 0; i < 4; ++i) {
            int idx = tid + 256*i, row = idx >> 3, q = idx & 7;
            __half hh[4], ll[4];
#pragma unroll
            for (int j = 0; j < 4; ++j) split2(ar[i*4+j], hh[j], ll[j]);
            char* base = sm + buf*STG + row*80 + q*8;
            *(uint2*)(base + 0*LIMB) = make_uint2(pkh(hh[0],hh[1]), pkh(hh[2],hh[3]));
            *(uint2*)(base + 1*LIMB) = make_uint2(pkh(ll[0],ll[1]), pkh(ll[2],ll[3]));
        }
    };
    auto cpB = [&](int buf, int kc) {
#pragma unroll
        for (int limb = 0; limb < 2; ++limb) {
            const __half* Bp = (limb == 0) ? B0 : B1;
#pragma unroll
            for (int i = 0; i < 2; ++i) {
                int r2 = tid + 256*i, row = r2 >> 2, cq = r2 & 3;
                uint32_t dst = sb + buf*STG + SBOFF + limb*LIMB + row*80 + cq*16;
                cpasync16(dst, Bp + (cCol + row)*KDIM + kc + cq*8);
            }
        }
    };
    auto compute = [&](int buf) {
#pragma unroll
        for (int h16 = 0; h16 < 2; ++h16) {
            const int kb = h16 * 32;
            uint32_t aF[2][4][4], bF[2][4][2];
#pragma unroll
            for (int limb = 0; limb < 2; ++limb) {
#pragma unroll
                for (int mt = 0; mt < 4; ++mt) {
                    int row = wr + mt*16 + (lane & 7) + ((lane >> 3) & 1)*8;
                    int boff = kb + (lane >> 4)*16;
                    ldm4(aF[limb][mt], sb + buf*STG + limb*LIMB + row*80 + boff);
                }
#pragma unroll
                for (int p = 0; p < 2; ++p) {
                    int row = wc + p*16 + (lane & 7) + ((lane >> 4) & 1)*8;
                    int boff = kb + ((lane >> 3) & 1)*16;
                    uint32_t r[4];
                    ldm4(r, sb + buf*STG + SBOFF + limb*LIMB + row*80 + boff);
                    bF[limb][p*2  ][0] = r[0]; bF[limb][p*2  ][1] = r[1];
                    bF[limb][p*2+1][0] = r[2]; bF[limb][p*2+1][1] = r[3];
                }
            }
#pragma unroll
            for (int mt = 0; mt < 4; ++mt)
#pragma unroll
                for (int nt = 0; nt < 4; ++nt) {
                    mma_f16(acc0[mt][nt], aF[0][mt], bF[0][nt]);
                    mma_f16(acc1[mt][nt], aF[0][mt], bF[1][nt]);
                    mma_f16(acc1[mt][nt], aF[1][mt], bF[0][nt]);
                }
        }
    };

    // ---- pipeline ----
    ldgA(0);
    cpB(0, 0);
    asm volatile("cp.async.commit_group;" ::: "memory");
    stsA(0);
    asm volatile("cp.async.wait_group 0;" ::: "memory");
    __syncthreads();
    int buf = 0;
#pragma unroll 1
    for (int s = 0; s < NS; ++s) {
        if (s + 1 < NS) {
            ldgA((s+1) * 32);
            cpB(buf ^ 1, (s+1) * 32);
            asm volatile("cp.async.commit_group;" ::: "memory");
        }
        compute(buf);
        if (s + 1 < NS) {
            stsA(buf ^ 1);
            asm volatile("cp.async.wait_group 0;" ::: "memory");
            __syncthreads();
            buf ^= 1;
        }
    }

    // ---- epilogue ----
    const int g4 = lane >> 2, q2 = (lane & 3) * 2;
#pragma unroll
    for (int mt = 0; mt < 4; ++mt) {
#pragma unroll
        for (int nt = 0; nt < 4; ++nt) {
#pragma unroll
            for (int half = 0; half < 2; ++half) {
                int rg = cRow + wr + mt*16 + g4 + half*8;
                int c  = cCol + wc + nt*8 + q2;
                float v0 = acc0[mt][nt][half*2]   + acc1[mt][nt][half*2]   * (1.f/2048.f);
                float v1 = acc0[mt][nt][half*2+1] + acc1[mt][nt][half*2+1] * (1.f/2048.f);
                if (MODE == 0) {
                    int b = rg >> 8, k = rg & 255;
                    const float* cz = g_cbz + (m*K_ + k)*D_ + c;
                    const float* yy = g_y + b*D_ + c;
                    v0 += cz[0] + yy[0]; v1 += cz[1] + yy[1];
                    *(float2*)(g_z + rg*D_ + c) = make_float2(v0, v1);
                } else if (MODE == 1) {
                    v0 = fmaxf(v0, 0.f); v1 = fmaxf(v1, 0.f);
                    *(float2*)(g_h + rg*H_ + c) = make_float2(v0, v1);
                } else {
                    float2 z = *(float2*)(g_z + rg*D_ + c);
                    *(float2*)(g_z + rg*D_ + c) = make_float2(z.x + v0, z.y + v1);
                }
            }
        }
    }
}

// ================= f32x2 exact SGEMM accumulator core (128x128 tile) =================
template <int K, int WS>
__device__ __forceinline__ void gemm_acc(const float* __restrict__ A,
                                         const float* __restrict__ W,
                                         float out[8][8]) {
    __shared__ float As[2][8][128];
    __shared__ float Bs[2][8][128];
    const int tid  = threadIdx.x;
    const int cRow = blockIdx.y * 128;
    const int cCol = blockIdx.x * 128;
    const int tRow = (tid >> 4) * 8;
    const int tCol = (tid & 15) * 8;
    const int rA = tid >> 1;
    const int cA = (tid & 1) * 4;

    uint64_t acc2[8][4] = {};
    const float* Ap = A + (cRow + rA) * K + cA;
    const float* Wp = W + (cCol + rA) * WS + cA;

    float4 a4 = *(const float4*)Ap;
    float4 b4 = *(const float4*)Wp;
    As[0][cA+0][rA]=a4.x; As[0][cA+1][rA]=a4.y; As[0][cA+2][rA]=a4.z; As[0][cA+3][rA]=a4.w;
    Bs[0][cA+0][rA]=b4.x; Bs[0][cA+1][rA]=b4.y; Bs[0][cA+2][rA]=b4.z; Bs[0][cA+3][rA]=b4.w;
    __syncthreads();

    constexpr int NT = K / 8;
    int buf = 0;
#pragma unroll 1
    for (int it = 0; it < NT; ++it) {
        float4 an, bn;
        if (it + 1 < NT) {
            an = *(const float4*)(Ap + (it + 1) * 8);
            bn = *(const float4*)(Wp + (it + 1) * 8);
        }
#pragma unroll
        for (int kk = 0; kk < 8; ++kk) {
            float rm[8];
            *(float4*)(rm)   = *(const float4*)&As[buf][kk][tRow];
            *(float4*)(rm+4) = *(const float4*)&As[buf][kk][tRow+4];
            uint64_t rn2[4];
            *(uint4*)(&rn2[0]) = *(const uint4*)&Bs[buf][kk][tCol];
            *(uint4*)(&rn2[2]) = *(const uint4*)&Bs[buf][kk][tCol+4];
#pragma unroll
            for (int i = 0; i < 8; ++i) {
                uint64_t am = dup2(rm[i]);
#pragma unroll
                for (int j = 0; j < 4; ++j) fma2(acc2[i][j], am, rn2[j]);
            }
        }
        if (it + 1 < NT) {
            int nb = buf ^ 1;
            As[nb][cA+0][rA]=an.x; As[nb][cA+1][rA]=an.y; As[nb][cA+2][rA]=an.z; As[nb][cA+3][rA]=an.w;
            Bs[nb][cA+0][rA]=bn.x; Bs[nb][cA+1][rA]=bn.y; Bs[nb][cA+2][rA]=bn.z; Bs[nb][cA+3][rA]=bn.w;
            __syncthreads();
            buf = nb;
        }
    }
#pragma unroll
    for (int i = 0; i < 8; ++i)
#pragma unroll
        for (int j = 0; j < 4; ++j) {
            float2 t = u2f(acc2[i][j]);
            out[i][2*j] = t.x; out[i][2*j+1] = t.y;
        }
}

// ---- precompute GEMMs (exact fp32) ----
__global__ void __launch_bounds__(256) k_cbzg(const float* __restrict__ cbs,
                                              const float* __restrict__ Wc,
                                              const float* __restrict__ bc) {
    int m = blockIdx.z;   // grid (1, 2, 7)
    float acc[8][8];
    const float* A = cbs + m * K_ * D_;
    gemm_acc<128, 256>(A, Wc + m * D_ * 2 * D_, acc);
    const int tid = threadIdx.x, cRow = blockIdx.y * 128;
    const int tRow = (tid >> 4) * 8, tCol = (tid & 15) * 8;
#pragma unroll
    for (int i = 0; i < 8; ++i)
#pragma unroll
        for (int j = 0; j < 8; ++j) {
            int r = cRow + tRow + i, c = tCol + j;
            g_cbz[(m * K_ + r) * D_ + c] = acc[i][j] + A[r * D_ + c] + bc[m * D_ + c];
        }
}
__global__ void __launch_bounds__(256) k_p1g(const float* __restrict__ W1) {
    int m = blockIdx.z;   // grid (2, 2, 7)  — cCol applied inside gemm_acc
    float acc[8][8];
    gemm_acc<128, 128>(g_cbz + m * K_ * D_, W1 + (m * 2) * H_ * D_, acc);
    const int tid = threadIdx.x, cRow = blockIdx.y * 128, cCol = blockIdx.x * 128;
    const int tRow = (tid >> 4) * 8, tCol = (tid & 15) * 8;
#pragma unroll
    for (int i = 0; i < 8; ++i)
#pragma unroll
        for (int j = 0; j < 8; ++j)
            g_P1[(m * K_ + cRow + tRow + i) * H_ + cCol + tCol + j] = acc[i][j];
}
__global__ void __launch_bounds__(256) k_yg(const float* __restrict__ Wc, int m, int ping) {
    float acc[8][8];
    gemm_acc<128, 256>(ping ? g_xb : g_xa, Wc + m * D_ * 2 * D_ + D_, acc);  // grid (1, 8)
    const int tid = threadIdx.x, cRow = blockIdx.y * 128;
    const int tRow = (tid >> 4) * 8, tCol = (tid & 15) * 8;
#pragma unroll
    for (int i = 0; i < 8; ++i)
#pragma unroll
        for (int j = 0; j < 8; ++j)
            g_y[(cRow + tRow + i) * D_ + tCol + j] = acc[i][j];
}
__global__ void __launch_bounds__(256) k_q1g(const float* __restrict__ W1, int m) {
    float acc[8][8];
    gemm_acc<128, 128>(g_y, W1 + (m * 2) * H_ * D_, acc);  // grid (2, 8) — cCol inside
    const int tid = threadIdx.x, cRow = blockIdx.y * 128, cCol = blockIdx.x * 128;
    const int tRow = (tid >> 4) * 8, tCol = (tid & 15) * 8;
#pragma unroll
    for (int i = 0; i < 8; ++i)
#pragma unroll
        for (int j = 0; j < 8; ++j)
            g_Q1[(cRow + tRow + i) * H_ + cCol + tCol + j] = acc[i][j];
}

// ---- winner recompute chain (exact fp32, batched over the 1024 selected rows) ----
__global__ void kw_h0(int m) {
    int i = blockIdx.x * 256 + threadIdx.x;    // 1024 blocks
    int b = i >> 8, h = i & 255;
    int k = g_code[b];
    g_h0w[i] = fmaxf(g_P1[(m * K_ + k) * H_ + h] + g_Q1[b * H_ + h], 0.f);
}
__global__ void __launch_bounds__(256) kw_g2(const float* __restrict__ W2, int m) {
    float acc[8][8];
    gemm_acc<256, 256>(g_h0w, W2 + 2 * m * 32768, acc);   // grid (1, 8)
    const int tid = threadIdx.x, cRow = blockIdx.y * 128;
    const int tRow = (tid >> 4) * 8, tCol = (tid & 15) * 8;
#pragma unroll
    for (int i = 0; i < 8; ++i) {
        int b = cRow + tRow + i;
        int k = g_code[b];
#pragma unroll
        for (int j = 0; j < 8; ++j) {
            int c = tCol + j;
            g_z1w[b * D_ + c] = acc[i][j] + g_cbz[(m * K_ + k) * D_ + c] + g_y[b * D_ + c];
        }
    }
}
__global__ void __launch_bounds__(256) kw_g3(const float* __restrict__ W1, int m) {
    float acc[8][8];
    gemm_acc<128, 128>(g_z1w, W1 + (2 * m + 1) * 32768, acc);  // grid (2, 8) — cCol inside
    const int tid = threadIdx.x, cRow = blockIdx.y * 128, cCol = blockIdx.x * 128;
    const int tRow = (tid >> 4) * 8, tCol = (tid & 15) * 8;
#pragma unroll
    for (int i = 0; i < 8; ++i)
#pragma unroll
        for (int j = 0; j < 8; ++j)
            g_h1w[(cRow + tRow + i) * H_ + cCol + tCol + j] = fmaxf(acc[i][j], 0.f);
}
__global__ void __launch_bounds__(256) kw_g4(const float* __restrict__ W2,
                                             float* __restrict__ out, int m, int ping) {
    float acc[8][8];
    gemm_acc<256, 256>(g_h1w, W2 + (2 * m + 1) * 32768, acc);   // grid (1, 8)
    const float* xin  = ping ? g_xb : g_xa;
    float*       xout = ping ? g_xa : g_xb;
    const int tid = threadIdx.x, cRow = blockIdx.y * 128;
    const int tRow = (tid >> 4) * 8, tCol = (tid & 15) * 8;
#pragma unroll
    for (int i = 0; i < 8; ++i) {
        int b = cRow + tRow + i;
#pragma unroll
        for (int j = 0; j < 8; ++j) {
            int c = tCol + j;
            float v = acc[i][j] + g_z1w[b * D_ + c] + xin[b * D_ + c];
            xout[b * D_ + c] = v;
            out[OUT_SIDE + (m + 1) * SIDE_SZ + b * D_ + c] = v;
            if (m == M_ - 2) out[b * D_ + c] = v;
        }
    }
}

// ================= step 0 (exact fp32) =================
__global__ void k_step0(const float* __restrict__ x, const float* __restrict__ cb0,
                        float* __restrict__ out) {
    int b = blockIdx.x, t = threadIdx.x;
    int w = t >> 5, lane = t & 31;
    __shared__ float4 xs[32];
    __shared__ float  sd[256];
    __shared__ int    si[256];
    if (t < 32) xs[t] = ((const float4*)x)[b * 32 + t];
    __syncthreads();
    float4 xv = xs[lane];
    for (int i = 0; i < 32; ++i) {
        int k = w * 32 + i;
        float4 c = ((const float4*)cb0)[k * 32 + lane];
        float a1 = c.x*c.x + c.y*c.y + c.z*c.z + c.w*c.w;
        float a2 = xv.x*c.x + xv.y*c.y + xv.z*c.z + xv.w*c.w;
        warp_red2(a1, a2);
        if (lane == 0) sd[k] = a1 - 2.f * a2;
    }
    si[t] = t;
    __syncthreads();
    for (int s = 128; s; s >>= 1) {
        if (t < s) {
            float o = sd[t + s]; int oi = si[t + s];
            if (o < sd[t] || (o == sd[t] && oi < si[t])) { sd[t] = o; si[t] = oi; }
        }
        __syncthreads();
    }
    int kb = si[0];
    if (t < D_) {
        float v = cb0[kb * D_ + t];
        g_xa[b * D_ + t] = v;
        out[OUT_SIDE + b * D_ + t] = v;       // side[0]
    }
    if (t == 0) out[OUT_CODES + b * M_] = (float)kb;
}

// ================= argmin select (fast dists) + candidate list =================
__global__ void k_argsel(const float* __restrict__ x, float* __restrict__ out,
                         int m, int ping) {
    const float* xin = ping ? g_xb : g_xa;
    int b = blockIdx.x, t = threadIdx.x;
    int w = t >> 5, lane = t & 31;
    __shared__ float4 xs[32], hs[32];
    __shared__ float  sd[256], sr[256];
    __shared__ int    si[256];
    __shared__ int    cnt;
    if (t < 32) {
        xs[t] = ((const float4*)x)[b * 32 + t];
        hs[t] = ((const float4*)xin)[b * 32 + t];
    }
    if (t == 0) cnt = 0;
    __syncthreads();
    float4 xv = xs[lane], hv = hs[lane];
    const float4* zr = (const float4*)g_z + b * (K_ * 32);
    for (int i = 0; i < 32; ++i) {
        int k = w * 32 + i;
        float4 z = zr[k * 32 + lane];
        z.x += hv.x; z.y += hv.y; z.z += hv.z; z.w += hv.w;
        float a1 = z.x*z.x + z.y*z.y + z.z*z.z + z.w*z.w;
        float a2 = xv.x*z.x + xv.y*z.y + xv.z*z.z + xv.w*z.w;
        warp_red2(a1, a2);
        if (lane == 0) sd[k] = a1 - 2.f * a2;
    }
    __syncthreads();
    sr[t] = sd[t];
    si[t] = t;
    __syncthreads();
    for (int s = 128; s; s >>= 1) {
        if (t < s) {
            float o = sr[t + s]; int oi = si[t + s];
            if (o < sr[t] || (o == sr[t] && oi < si[t])) { sr[t] = o; si[t] = oi; }
        }
        __syncthreads();
    }
    float d1 = sr[0];
    int   kb = si[0];
    // candidate list within TAU of min
    if (sd[t] <= d1 + TAU) {
        int pos = atomicAdd(&cnt, 1);
        if (pos < 16) g_clist[b * 16 + pos] = t;
    }
    __syncthreads();
    if (t == 0) {
        g_ccount[b] = cnt;
        if (cnt == 1) {
            g_code[b] = kb;
            out[OUT_CODES + b * M_ + m + 1] = (float)kb;
        }
    }
}

// ================= exact fp32 rescue for near-ties =================
__global__ void k_ties(const float* __restrict__ x, const float* __restrict__ W1,
                       const float* __restrict__ W2, float* __restrict__ out,
                       int m, int ping) {
    int b = blockIdx.x;
    int C = g_ccount[b];
    if (C <= 1) return;
    const float* xin = ping ? g_xb : g_xa;
    int t = threadIdx.x, lane = t & 31, wid = t >> 5;
    __shared__ float xh[128], xv[128], h0s[256], z1s[128], h1s[256], z2s[128];
    __shared__ float red[8];
    __shared__ float bestd;
    __shared__ int   bestk;
    if (t < 128) { xh[t] = xin[b * 128 + t]; xv[t] = x[b * 128 + t]; }
    if (t == 0) { bestd = 3.4e38f; bestk = 0x7fffffff; }
    __syncthreads();
    bool all = (C > 16);
    int n = all ? 256 : C;
    const float* W2_0 = W2 + (2 * m) * 32768;
    const float* W1_1 = W1 + (2 * m + 1) * 32768;
    const float* W2_1 = W2 + (2 * m + 1) * 32768;
    for (int i = 0; i < n; ++i) {
        int k = all ? i : g_clist[b * 16 + i];
        h0s[t] = fmaxf(g_P1[(m * K_ + k) * H_ + t] + g_Q1[b * H_ + t], 0.f);
        __syncthreads();
        for (int it = 0; it < 16; ++it) {       // z1
            int d = it * 8 + wid;
            float a = 0.f;
            const float* wrow = W2_0 + d * 256;
#pragma unroll
            for (int j = 0; j < 8; ++j) a += wrow[lane + 32*j] * h0s[lane + 32*j];
#pragma unroll
            for (int o = 16; o; o >>= 1) a += __shfl_xor_sync(~0u, a, o);
            if (lane == 0) z1s[d] = g_cbz[(m * K_ + k) * D_ + d] + g_y[b * D_ + d] + a;
        }
        __syncthreads();
        for (int it = 0; it < 32; ++it) {       // h1
            int h = it * 8 + wid;
            float a = 0.f;
            const float* wrow = W1_1 + h * 128;
#pragma unroll
            for (int j = 0; j < 4; ++j) a += wrow[lane + 32*j] * z1s[lane + 32*j];
#pragma unroll
            for (int o = 16; o; o >>= 1) a += __shfl_xor_sync(~0u, a, o);
            if (lane == 0) h1s[h] = fmaxf(a, 0.f);
        }
        __syncthreads();
        for (int it = 0; it < 16; ++it) {       // z2
            int d = it * 8 + wid;
            float a = 0.f;
            const float* wrow = W2_1 + d * 256;
#pragma unroll
            for (int j = 0; j < 8; ++j) a += wrow[lane + 32*j] * h1s[lane + 32*j];
#pragma unroll
            for (int o = 16; o; o >>= 1) a += __shfl_xor_sync(~0u, a, o);
            if (lane == 0) z2s[d] = z1s[d] + a;
        }
        __syncthreads();
        float p = 0.f;
        if (t < 128) { float zf = z2s[t] + xh[t]; p = zf*zf - 2.f*xv[t]*zf; }
#pragma unroll
        for (int o = 16; o; o >>= 1) p += __shfl_xor_sync(~0u, p, o);
        if (lane == 0) red[wid] = p;
        __syncthreads();
        if (t == 0) {
            float d = red[0] + red[1] + red[2] + red[3];
            if (d < bestd || (d == bestd && k < bestk)) { bestd = d; bestk = k; }
        }
        __syncthreads();
    }
    if (t == 0) {
        g_code[b] = bestk;
        out[OUT_CODES + b * M_ + m + 1] = (float)bestk;
    }
}

extern "C" void kernel_launch(void* const* d_in, const int* in_sizes, int n_in,
                              void* d_out, int out_size) {
    const float* x   = (const float*)d_in[0];
    const float* cb0 = (const float*)d_in[1];
    const float* cbs = (const float*)d_in[2];
    const float* Wc  = (const float*)d_in[3];
    const float* bc  = (const float*)d_in[4];
    const float* W1  = (const float*)d_in[5];
    const float* W2  = (const float*)d_in[6];
    float* out = (float*)d_out;

    cudaFuncSetAttribute(k_mma<0>, cudaFuncAttributeMaxDynamicSharedMemorySize, SMEM_MMA);
    cudaFuncSetAttribute(k_mma<1>, cudaFuncAttributeMaxDynamicSharedMemorySize, SMEM_MMA);
    cudaFuncSetAttribute(k_mma<2>, cudaFuncAttributeMaxDynamicSharedMemorySize, SMEM_MMA);

    // weight-only precomputes
    k_splitw<<<1792, 256>>>(W1, W2);
    k_cbzg<<<dim3(1, 2, 7), 256>>>(cbs, Wc, bc);
    k_p1g<<<dim3(2, 2, 7), 256>>>(W1);
    k_step0<<<BS_, 256>>>(x, cb0, out);

    int ping = 0;   // xhat currently in g_xa
    for (int m = 0; m < M_ - 1; ++m) {
        k_yg<<<dim3(1, 8), 256>>>(Wc, m, ping);
        k_q1g<<<dim3(2, 8), 256>>>(W1, m);
        // fast candidate path (fp16 2-limb, 3 mma passes)
        k_mma<0><<<dim3(1, NR / 128), 256, SMEM_MMA>>>(m);
        k_mma<1><<<dim3(2, NR / 128), 256, SMEM_MMA>>>(m);
        k_mma<2><<<dim3(1, NR / 128), 256, SMEM_MMA>>>(m);
        // selection: fast dists + exact rescue for near-ties
        k_argsel<<<BS_, 256>>>(x, out, m, ping);
        k_ties<<<BS_, 256>>>(x, W1, W2, out, m, ping);
        // exact fp32 winner recompute -> xhat, side, (final xhat)
        kw_h0<<<BS_, 256>>>(m);
        kw_g2<<<dim3(1, 8), 256>>>(W2, m);
        kw_g3<<<dim3(2, 8), 256>>>(W1, m);
        kw_g4<<<dim3(1, 8), 256>>>(W2, out, m, ping);
        ping ^= 1;
    }
}

// round 9
// speedup vs baseline: 2.0678x; 1.4122x over previous
#include <cuda_runtime.h>
#include <cuda_fp16.h>
#include <stdint.h>

// QINCo: D=128, M=8, K=256, L=2, H=256, BS=1024
namespace {
constexpr int D_  = 128;
constexpr int K_  = 256;
constexpr int M_  = 8;
constexpr int H_  = 256;
constexpr int BS_ = 1024;
constexpr int NR  = BS_ * K_;                   // 262144

constexpr int OUT_CODES = BS_ * D_;             // 131072
constexpr int OUT_SIDE  = OUT_CODES + BS_ * M_; // 139264
constexpr int SIDE_SZ   = BS_ * D_;

constexpr int CH = 10240;                       // one limb chunk: 128 rows * 80B
// fused-kernel smem layout
constexpr int Z0_OFF = 0;                       // 4 chunks * 2 limbs * CH = 81920
constexpr int H_OFF  = 81920;                   // 4 chunks * 2 limbs (also phase-A A staging)
constexpr int WS_OFF = 163840;                  // 2 bufs * 2 limbs * CH = 40960
constexpr int SMEM_F = 204800;

constexpr float TAU   = 1e-2f;
constexpr float INV64 = 1.0f / 64.0f;
}

// ---- device scratch (allocation-free) ----
__device__ __align__(128) float g_cbz[(M_-1) * K_ * D_];
__device__ __align__(128) float g_P1[(M_-1) * K_ * H_];
__device__ __align__(128) float g_y[BS_ * D_];
__device__ __align__(128) float g_Q1[BS_ * H_];
__device__ __align__(128) float g_xa[BS_ * D_];
__device__ __align__(128) float g_xb[BS_ * D_];
__device__ __align__(128) float g_dist[NR];
// fp16 2-limb weights (pre-scaled x64): W1 layer-1 [7][256][128]; W2 [14][128][256]
__device__ __align__(128) __half g_w1a[7*32768], g_w1b[7*32768];
__device__ __align__(128) __half g_w2a[14*32768], g_w2b[14*32768];
// winner / rescue machinery
__device__ __align__(128) float g_h0w[BS_ * H_];
__device__ __align__(128) float g_z1w[BS_ * D_];
__device__ __align__(128) float g_h1w[BS_ * H_];
__device__ int g_code[BS_];
__device__ int g_ccount[BS_];
__device__ int g_clist[BS_ * 16];

// ================= helpers =================
__device__ __forceinline__ uint32_t smem_u32(const void* p) {
    uint32_t a;
    asm("{ .reg .u64 t; cvta.to.shared.u64 t, %1; cvt.u32.u64 %0, t; }" : "=r"(a) : "l"(p));
    return a;
}
__device__ __forceinline__ void split2(float a, __half& h, __half& l) {
    h = __float2half_rn(a);
    l = __float2half_rn(a - __half2float(h));   // unscaled low limb
}
__device__ __forceinline__ uint32_t pkh(__half a, __half b) {
    return (uint32_t)__half_as_ushort(a) | ((uint32_t)__half_as_ushort(b) << 16);
}
__device__ __forceinline__ void warp_red2(float& a, float& b) {
#pragma unroll
    for (int o = 16; o; o >>= 1) {
        a += __shfl_xor_sync(0xffffffffu, a, o);
        b += __shfl_xor_sync(0xffffffffu, b, o);
    }
}
__device__ __forceinline__ void mma_f16(float* c, const uint32_t* a, const uint32_t* b) {
    asm volatile("mma.sync.aligned.m16n8k16.row.col.f32.f16.f16.f32 "
        "{%0,%1,%2,%3}, {%4,%5,%6,%7}, {%8,%9}, {%0,%1,%2,%3};"
        : "+f"(c[0]), "+f"(c[1]), "+f"(c[2]), "+f"(c[3])
        : "r"(a[0]), "r"(a[1]), "r"(a[2]), "r"(a[3]), "r"(b[0]), "r"(b[1]));
}
__device__ __forceinline__ void ldm4(uint32_t* r, uint32_t addr) {
    asm volatile("ldmatrix.sync.aligned.m8n8.x4.shared.b16 {%0,%1,%2,%3}, [%4];"
        : "=r"(r[0]), "=r"(r[1]), "=r"(r[2]), "=r"(r[3]) : "r"(addr));
}
__device__ __forceinline__ void cpasync16(uint32_t s, const void* g) {
    asm volatile("cp.async.cg.shared.global [%0], [%1], 16;" :: "r"(s), "l"(g));
}
#define CP_COMMIT() asm volatile("cp.async.commit_group;" ::: "memory")
#define CP_WAIT0()  asm volatile("cp.async.wait_group 0;" ::: "memory")
// packed fp32 (for small exact GEMMs)
__device__ __forceinline__ uint64_t dup2(float x) {
    uint64_t r; asm("mov.b64 %0, {%1, %1};" : "=l"(r) : "f"(x)); return r;
}
__device__ __forceinline__ void fma2(uint64_t& d, uint64_t a, uint64_t b) {
    asm("fma.rn.f32x2 %0, %1, %2, %0;" : "+l"(d) : "l"(a), "l"(b));
}
__device__ __forceinline__ float2 u2f(uint64_t v) {
    float2 r; asm("mov.b64 {%0, %1}, %2;" : "=f"(r.x), "=f"(r.y) : "l"(v)); return r;
}

// ================= weight limb split (x64 pre-scale, once per launch) =================
__global__ void k_splitw(const float* __restrict__ W1, const float* __restrict__ W2) {
    int i = blockIdx.x * 256 + threadIdx.x;
    if (i < 7 * 32768) {
        int mm = i / 32768, r = i % 32768;
        __half h, l;
        split2(64.0f * W1[(mm * 2 + 1) * 32768 + r], h, l);
        g_w1a[i] = h; g_w1b[i] = l;
    }
    if (i < 14 * 32768) {
        __half h, l;
        split2(64.0f * W2[i], h, l);
        g_w2a[i] = h; g_w2b[i] = l;
    }
}

// ================= fused per-step fast path =================
// One CTA = 128 candidates (one half of one batch row b).
// Phase A: z0 = base + relu(P1+Q1) @ W2_0^T          (K=256)
// Phase B: h_half = relu(z0 @ W1_1^T[half])          (K=128, x2 halves)
// Phase C: z2 += h_half @ W2_1^T[half rows]          (K=128 per half)
// Epilogue: dist[k] = |zf|^2 - 2 x.zf,  zf = z0 + z2 + xhat
__global__ void __launch_bounds__(256, 1) k_fused(const float* __restrict__ x,
                                                  int m, int ping) {
    extern __shared__ char sm[];
    uint32_t sb = smem_u32(sm);
    const int tid = threadIdx.x, lane = tid & 31, wid = tid >> 5;
    const int wr = (wid >> 2) * 64;
    const int wcn = wid & 3, wc = wcn * 32;
    const int g4 = lane >> 2, q2 = (lane & 3) * 2;
    const int bx = blockIdx.x;
    const int b = bx >> 1, k0 = (bx & 1) * 128;

    float z2[4][4][4] = {};
    float ar[16];

    // --- generic 32-wide chunk compute: 3 passes into single acc ---
    auto mma_chunk = [&](float acc[4][4][4], uint32_t aB0, uint32_t aB1,
                         uint32_t bB0, uint32_t bB1) {
#pragma unroll
        for (int h16 = 0; h16 < 2; ++h16) {
            const int kb = h16 * 32;
            uint32_t aF[2][4][4], bF[2][4][2];
#pragma unroll
            for (int limb = 0; limb < 2; ++limb) {
                uint32_t aB = limb ? aB1 : aB0;
                uint32_t bB = limb ? bB1 : bB0;
#pragma unroll
                for (int mt = 0; mt < 4; ++mt)
                    ldm4(aF[limb][mt], aB + (wr + mt*16 + (lane & 15))*80 + kb + (lane >> 4)*16);
#pragma unroll
                for (int p = 0; p < 2; ++p) {
                    uint32_t r[4];
                    ldm4(r, bB + (wc + p*16 + (lane & 7) + ((lane >> 4) & 1)*8)*80 + kb + ((lane >> 3) & 1)*16);
                    bF[limb][p*2  ][0] = r[0]; bF[limb][p*2  ][1] = r[1];
                    bF[limb][p*2+1][0] = r[2]; bF[limb][p*2+1][1] = r[3];
                }
            }
#pragma unroll
            for (int mt = 0; mt < 4; ++mt)
#pragma unroll
                for (int nt = 0; nt < 4; ++nt) {
                    mma_f16(acc[mt][nt], aF[0][mt], bF[0][nt]);
                    mma_f16(acc[mt][nt], aF[0][mt], bF[1][nt]);
                    mma_f16(acc[mt][nt], aF[1][mt], bF[0][nt]);
                }
        }
    };
    // --- weight-chunk loader (128 rows x 32 cols, both limbs) ---
    auto cpW = [&](const __half* Wh, const __half* Wl, int stride, int colOff, int buf) {
#pragma unroll
        for (int limb = 0; limb < 2; ++limb) {
            const __half* src = limb ? Wl : Wh;
#pragma unroll
            for (int i = 0; i < 2; ++i) {
                int r2 = tid + 256*i, row = r2 >> 2, cq = r2 & 3;
                cpasync16(sb + WS_OFF + (buf*2 + limb)*CH + row*80 + cq*16,
                          src + row*stride + colOff + cq*8);
            }
        }
    };
    // --- phase A: A-operand = relu(P1+Q1), loaded+split per chunk ---
    auto ldgA = [&](int ch) {
#pragma unroll
        for (int i = 0; i < 4; ++i) {
            int idx = tid + 256*i, row = idx >> 3, q = idx & 7;
            int kk = k0 + row;
            float4 p  = *(const float4*)(g_P1 + ((m << 8) + kk)*H_ + ch*32 + q*4);
            float4 qq = *(const float4*)(g_Q1 + b*H_ + ch*32 + q*4);
            ar[i*4+0] = fmaxf(p.x + qq.x, 0.f);
            ar[i*4+1] = fmaxf(p.y + qq.y, 0.f);
            ar[i*4+2] = fmaxf(p.z + qq.z, 0.f);
            ar[i*4+3] = fmaxf(p.w + qq.w, 0.f);
        }
    };
    auto stsA = [&](int buf) {
#pragma unroll
        for (int i = 0; i < 4; ++i) {
            int idx = tid + 256*i, row = idx >> 3, q = idx & 7;
            __half hh[4], ll[4];
#pragma unroll
            for (int j = 0; j < 4; ++j) split2(ar[i*4+j], hh[j], ll[j]);
            char* base = sm + H_OFF + (buf*2)*CH + row*80 + q*8;
            *(uint2*)(base)      = make_uint2(pkh(hh[0],hh[1]), pkh(hh[2],hh[3]));
            *(uint2*)(base + CH) = make_uint2(pkh(ll[0],ll[1]), pkh(ll[2],ll[3]));
        }
    };

    // ================= phase A =================
    {
        float za[4][4][4] = {};
        const __half* WA = g_w2a + 2*m*32768;
        const __half* WB = g_w2b + 2*m*32768;
        ldgA(0);
        cpW(WA, WB, 256, 0, 0);
        CP_COMMIT();
        stsA(0);
        CP_WAIT0();
        __syncthreads();
        int buf = 0;
#pragma unroll 1
        for (int ch = 0; ch < 8; ++ch) {
            if (ch + 1 < 8) {
                ldgA(ch + 1);
                cpW(WA, WB, 256, (ch + 1)*32, buf ^ 1);
                CP_COMMIT();
            }
            mma_chunk(za, sb + H_OFF + (buf*2)*CH, sb + H_OFF + (buf*2+1)*CH,
                          sb + WS_OFF + (buf*2)*CH, sb + WS_OFF + (buf*2+1)*CH);
            if (ch + 1 < 8) {
                stsA(buf ^ 1);
                CP_WAIT0();
                __syncthreads();
                buf ^= 1;
            }
        }
        __syncthreads();
        // epilogue: z0 = za/64 + cbz + y  -> split into Z0 limb chunks
#pragma unroll
        for (int mt = 0; mt < 4; ++mt)
#pragma unroll
            for (int half = 0; half < 2; ++half) {
                int row = wr + mt*16 + g4 + half*8;
#pragma unroll
                for (int nt = 0; nt < 4; ++nt) {
                    int col = wc + nt*8 + q2;
                    float2 cz = *(const float2*)(g_cbz + ((m << 8) + k0 + row)*D_ + col);
                    float2 yy = *(const float2*)(g_y + b*D_ + col);
                    float v0 = za[mt][nt][half*2]   * INV64 + cz.x + yy.x;
                    float v1 = za[mt][nt][half*2+1] * INV64 + cz.y + yy.y;
                    __half h0, l0, h1, l1;
                    split2(v0, h0, l0); split2(v1, h1, l1);
                    uint32_t off = (uint32_t)(((col >> 5)*2)*CH + row*80 + (col & 31)*2);
                    *(uint32_t*)(sm + Z0_OFF + off)      = pkh(h0, h1);
                    *(uint32_t*)(sm + Z0_OFF + off + CH) = pkh(l0, l1);
                }
            }
        __syncthreads();
    }

    // ================= phases B/C per 128-col half =================
#pragma unroll 1
    for (int nh = 0; nh < 2; ++nh) {
        { // phase B: h_half = relu(z0 @ W1_1^T[half])
            float ha[4][4][4] = {};
            const __half* WA = g_w1a + m*32768 + nh*128*128;
            const __half* WB = g_w1b + m*32768 + nh*128*128;
            cpW(WA, WB, 128, 0, 0);
            CP_COMMIT(); CP_WAIT0(); __syncthreads();
            int buf = 0;
#pragma unroll 1
            for (int ch = 0; ch < 4; ++ch) {
                if (ch + 1 < 4) {
                    cpW(WA, WB, 128, (ch + 1)*32, buf ^ 1);
                    CP_COMMIT();
                }
                mma_chunk(ha, sb + Z0_OFF + (ch*2)*CH, sb + Z0_OFF + (ch*2+1)*CH,
                              sb + WS_OFF + (buf*2)*CH, sb + WS_OFF + (buf*2+1)*CH);
                if (ch + 1 < 4) {
                    CP_WAIT0(); __syncthreads(); buf ^= 1;
                }
            }
            __syncthreads();
            // relu + split -> H limb chunks
#pragma unroll
            for (int mt = 0; mt < 4; ++mt)
#pragma unroll
                for (int half = 0; half < 2; ++half) {
                    int row = wr + mt*16 + g4 + half*8;
#pragma unroll
                    for (int nt = 0; nt < 4; ++nt) {
                        int col = wc + nt*8 + q2;
                        float v0 = fmaxf(ha[mt][nt][half*2]   * INV64, 0.f);
                        float v1 = fmaxf(ha[mt][nt][half*2+1] * INV64, 0.f);
                        __half h0, l0, h1, l1;
                        split2(v0, h0, l0); split2(v1, h1, l1);
                        uint32_t off = (uint32_t)(((col >> 5)*2)*CH + row*80 + (col & 31)*2);
                        *(uint32_t*)(sm + H_OFF + off)      = pkh(h0, h1);
                        *(uint32_t*)(sm + H_OFF + off + CH) = pkh(l0, l1);
                    }
                }
            __syncthreads();
        }
        { // phase C: z2 += h_half @ W2_1^T[half rows]
            const __half* WA = g_w2a + (2*m + 1)*32768;
            const __half* WB = g_w2b + (2*m + 1)*32768;
            cpW(WA, WB, 256, nh*128, 0);
            CP_COMMIT(); CP_WAIT0(); __syncthreads();
            int buf = 0;
#pragma unroll 1
            for (int ch = 0; ch < 4; ++ch) {
                if (ch + 1 < 4) {
                    cpW(WA, WB, 256, nh*128 + (ch + 1)*32, buf ^ 1);
                    CP_COMMIT();
                }
                mma_chunk(z2, sb + H_OFF + (ch*2)*CH, sb + H_OFF + (ch*2+1)*CH,
                              sb + WS_OFF + (buf*2)*CH, sb + WS_OFF + (buf*2+1)*CH);
                if (ch + 1 < 4) {
                    CP_WAIT0(); __syncthreads(); buf ^= 1;
                }
            }
            __syncthreads();
        }
    }

    // ================= dist epilogue =================
    const float* xin = ping ? g_xb : g_xa;
    float p8[8];
#pragma unroll
    for (int mt = 0; mt < 4; ++mt)
#pragma unroll
        for (int half = 0; half < 2; ++half) {
            int row = wr + mt*16 + g4 + half*8;
            float p = 0.f;
#pragma unroll
            for (int nt = 0; nt < 4; ++nt) {
                int col = wc + nt*8 + q2;
                uint32_t off = (uint32_t)(((col >> 5)*2)*CH + row*80 + (col & 31)*2);
                uint32_t u0 = *(const uint32_t*)(sm + Z0_OFF + off);
                uint32_t u1 = *(const uint32_t*)(sm + Z0_OFF + off + CH);
                float z0a = __half2float(__ushort_as_half((unsigned short)(u0 & 0xffff)))
                          + __half2float(__ushort_as_half((unsigned short)(u1 & 0xffff)));
                float z0b = __half2float(__ushort_as_half((unsigned short)(u0 >> 16)))
                          + __half2float(__ushort_as_half((unsigned short)(u1 >> 16)));
                float2 xh = *(const float2*)(xin + b*D_ + col);
                float2 xv = *(const float2*)(x + b*D_ + col);
                float zf0 = z0a + z2[mt][nt][half*2]   * INV64 + xh.x;
                float zf1 = z0b + z2[mt][nt][half*2+1] * INV64 + xh.y;
                p += zf0 * (zf0 - 2.f*xv.x) + zf1 * (zf1 - 2.f*xv.y);
            }
            p8[mt*2 + half] = p;
        }
#pragma unroll
    for (int j = 0; j < 8; ++j) {
        p8[j] += __shfl_xor_sync(0xffffffffu, p8[j], 1);
        p8[j] += __shfl_xor_sync(0xffffffffu, p8[j], 2);
    }
    float* sd = (float*)(sm + WS_OFF);
    if ((lane & 3) == 0) {
#pragma unroll
        for (int mt = 0; mt < 4; ++mt)
#pragma unroll
            for (int half = 0; half < 2; ++half)
                sd[(wr + mt*16 + g4 + half*8)*4 + wcn] = p8[mt*2 + half];
    }
    __syncthreads();
    if (tid < 128) {
        float s = sd[tid*4] + sd[tid*4+1] + sd[tid*4+2] + sd[tid*4+3];
        g_dist[bx*128 + tid] = s;
    }
}

// ================= f32x2 exact SGEMM accumulator core (128x128 tile) =================
template <int K, int WS>
__device__ __forceinline__ void gemm_acc(const float* __restrict__ A,
                                         const float* __restrict__ W,
                                         float out[8][8]) {
    __shared__ float As[2][8][128];
    __shared__ float Bs[2][8][128];
    const int tid  = threadIdx.x;
    const int cRow = blockIdx.y * 128;
    const int cCol = blockIdx.x * 128;
    const int tRow = (tid >> 4) * 8;
    const int tCol = (tid & 15) * 8;
    const int rA = tid >> 1;
    const int cA = (tid & 1) * 4;

    uint64_t acc2[8][4] = {};
    const float* Ap = A + (cRow + rA) * K + cA;
    const float* Wp = W + (cCol + rA) * WS + cA;

    float4 a4 = *(const float4*)Ap;
    float4 b4 = *(const float4*)Wp;
    As[0][cA+0][rA]=a4.x; As[0][cA+1][rA]=a4.y; As[0][cA+2][rA]=a4.z; As[0][cA+3][rA]=a4.w;
    Bs[0][cA+0][rA]=b4.x; Bs[0][cA+1][rA]=b4.y; Bs[0][cA+2][rA]=b4.z; Bs[0][cA+3][rA]=b4.w;
    __syncthreads();

    constexpr int NT = K / 8;
    int buf = 0;
#pragma unroll 1
    for (int it = 0; it < NT; ++it) {
        float4 an, bn;
        if (it + 1 < NT) {
            an = *(const float4*)(Ap + (it + 1) * 8);
            bn = *(const float4*)(Wp + (it + 1) * 8);
        }
#pragma unroll
        for (int kk = 0; kk < 8; ++kk) {
            float rm[8];
            *(float4*)(rm)   = *(const float4*)&As[buf][kk][tRow];
            *(float4*)(rm+4) = *(const float4*)&As[buf][kk][tRow+4];
            uint64_t rn2[4];
            *(uint4*)(&rn2[0]) = *(const uint4*)&Bs[buf][kk][tCol];
            *(uint4*)(&rn2[2]) = *(const uint4*)&Bs[buf][kk][tCol+4];
#pragma unroll
            for (int i = 0; i < 8; ++i) {
                uint64_t am = dup2(rm[i]);
#pragma unroll
                for (int j = 0; j < 4; ++j) fma2(acc2[i][j], am, rn2[j]);
            }
        }
        if (it + 1 < NT) {
            int nb = buf ^ 1;
            As[nb][cA+0][rA]=an.x; As[nb][cA+1][rA]=an.y; As[nb][cA+2][rA]=an.z; As[nb][cA+3][rA]=an.w;
            Bs[nb][cA+0][rA]=bn.x; Bs[nb][cA+1][rA]=bn.y; Bs[nb][cA+2][rA]=bn.z; Bs[nb][cA+3][rA]=bn.w;
            __syncthreads();
            buf = nb;
        }
    }
#pragma unroll
    for (int i = 0; i < 8; ++i)
#pragma unroll
        for (int j = 0; j < 4; ++j) {
            float2 t = u2f(acc2[i][j]);
            out[i][2*j] = t.x; out[i][2*j+1] = t.y;
        }
}

// ---- precompute GEMMs (exact fp32) ----
__global__ void __launch_bounds__(256) k_cbzg(const float* __restrict__ cbs,
                                              const float* __restrict__ Wc,
                                              const float* __restrict__ bc) {
    int m = blockIdx.z;   // grid (1, 2, 7)
    float acc[8][8];
    const float* A = cbs + m * K_ * D_;
    gemm_acc<128, 256>(A, Wc + m * D_ * 2 * D_, acc);
    const int tid = threadIdx.x, cRow = blockIdx.y * 128;
    const int tRow = (tid >> 4) * 8, tCol = (tid & 15) * 8;
#pragma unroll
    for (int i = 0; i < 8; ++i)
#pragma unroll
        for (int j = 0; j < 8; ++j) {
            int r = cRow + tRow + i, c = tCol + j;
            g_cbz[(m * K_ + r) * D_ + c] = acc[i][j] + A[r * D_ + c] + bc[m * D_ + c];
        }
}
__global__ void __launch_bounds__(256) k_p1g(const float* __restrict__ W1) {
    int m = blockIdx.z;   // grid (2, 2, 7) — cCol applied inside gemm_acc
    float acc[8][8];
    gemm_acc<128, 128>(g_cbz + m * K_ * D_, W1 + (m * 2) * H_ * D_, acc);
    const int tid = threadIdx.x, cRow = blockIdx.y * 128, cCol = blockIdx.x * 128;
    const int tRow = (tid >> 4) * 8, tCol = (tid & 15) * 8;
#pragma unroll
    for (int i = 0; i < 8; ++i)
#pragma unroll
        for (int j = 0; j < 8; ++j)
            g_P1[(m * K_ + cRow + tRow + i) * H_ + cCol + tCol + j] = acc[i][j];
}
__global__ void __launch_bounds__(256) k_yg(const float* __restrict__ Wc, int m, int ping) {
    float acc[8][8];
    gemm_acc<128, 256>(ping ? g_xb : g_xa, Wc + m * D_ * 2 * D_ + D_, acc);  // grid (1, 8)
    const int tid = threadIdx.x, cRow = blockIdx.y * 128;
    const int tRow = (tid >> 4) * 8, tCol = (tid & 15) * 8;
#pragma unroll
    for (int i = 0; i < 8; ++i)
#pragma unroll
        for (int j = 0; j < 8; ++j)
            g_y[(cRow + tRow + i) * D_ + tCol + j] = acc[i][j];
}
__global__ void __launch_bounds__(256) k_q1g(const float* __restrict__ W1, int m) {
    float acc[8][8];
    gemm_acc<128, 128>(g_y, W1 + (m * 2) * H_ * D_, acc);  // grid (2, 8) — cCol inside
    const int tid = threadIdx.x, cRow = blockIdx.y * 128, cCol = blockIdx.x * 128;
    const int tRow = (tid >> 4) * 8, tCol = (tid & 15) * 8;
#pragma unroll
    for (int i = 0; i < 8; ++i)
#pragma unroll
        for (int j = 0; j < 8; ++j)
            g_Q1[(cRow + tRow + i) * H_ + cCol + tCol + j] = acc[i][j];
}

// ---- winner recompute chain (exact fp32, batched over the 1024 selected rows) ----
__global__ void kw_h0(int m) {
    int i = blockIdx.x * 256 + threadIdx.x;    // 1024 blocks
    int b = i >> 8, h = i & 255;
    int k = g_code[b];
    g_h0w[i] = fmaxf(g_P1[(m * K_ + k) * H_ + h] + g_Q1[b * H_ + h], 0.f);
}
__global__ void __launch_bounds__(256) kw_g2(const float* __restrict__ W2, int m) {
    float acc[8][8];
    gemm_acc<256, 256>(g_h0w, W2 + 2 * m * 32768, acc);   // grid (1, 8)
    const int tid = threadIdx.x, cRow = blockIdx.y * 128;
    const int tRow = (tid >> 4) * 8, tCol = (tid & 15) * 8;
#pragma unroll
    for (int i = 0; i < 8; ++i) {
        int b = cRow + tRow + i;
        int k = g_code[b];
#pragma unroll
        for (int j = 0; j < 8; ++j) {
            int c = tCol + j;
            g_z1w[b * D_ + c] = acc[i][j] + g_cbz[(m * K_ + k) * D_ + c] + g_y[b * D_ + c];
        }
    }
}
__global__ void __launch_bounds__(256) kw_g3(const float* __restrict__ W1, int m) {
    float acc[8][8];
    gemm_acc<128, 128>(g_z1w, W1 + (2 * m + 1) * 32768, acc);  // grid (2, 8) — cCol inside
    const int tid = threadIdx.x, cRow = blockIdx.y * 128, cCol = blockIdx.x * 128;
    const int tRow = (tid >> 4) * 8, tCol = (tid & 15) * 8;
#pragma unroll
    for (int i = 0; i < 8; ++i)
#pragma unroll
        for (int j = 0; j < 8; ++j)
            g_h1w[(cRow + tRow + i) * H_ + cCol + tCol + j] = fmaxf(acc[i][j], 0.f);
}
__global__ void __launch_bounds__(256) kw_g4(const float* __restrict__ W2,
                                             float* __restrict__ out, int m, int ping) {
    float acc[8][8];
    gemm_acc<256, 256>(g_h1w, W2 + (2 * m + 1) * 32768, acc);   // grid (1, 8)
    const float* xin  = ping ? g_xb : g_xa;
    float*       xout = ping ? g_xa : g_xb;
    const int tid = threadIdx.x, cRow = blockIdx.y * 128;
    const int tRow = (tid >> 4) * 8, tCol = (tid & 15) * 8;
#pragma unroll
    for (int i = 0; i < 8; ++i) {
        int b = cRow + tRow + i;
#pragma unroll
        for (int j = 0; j < 8; ++j) {
            int c = tCol + j;
            float v = acc[i][j] + g_z1w[b * D_ + c] + xin[b * D_ + c];
            xout[b * D_ + c] = v;
            out[OUT_SIDE + (m + 1) * SIDE_SZ + b * D_ + c] = v;
            if (m == M_ - 2) out[b * D_ + c] = v;
        }
    }
}

// ================= step 0 (exact fp32) =================
__global__ void k_step0(const float* __restrict__ x, const float* __restrict__ cb0,
                        float* __restrict__ out) {
    int b = blockIdx.x, t = threadIdx.x;
    int w = t >> 5, lane = t & 31;
    __shared__ float4 xs[32];
    __shared__ float  sd[256];
    __shared__ int    si[256];
    if (t < 32) xs[t] = ((const float4*)x)[b * 32 + t];
    __syncthreads();
    float4 xv = xs[lane];
    for (int i = 0; i < 32; ++i) {
        int k = w * 32 + i;
        float4 c = ((const float4*)cb0)[k * 32 + lane];
        float a1 = c.x*c.x + c.y*c.y + c.z*c.z + c.w*c.w;
        float a2 = xv.x*c.x + xv.y*c.y + xv.z*c.z + xv.w*c.w;
        warp_red2(a1, a2);
        if (lane == 0) sd[k] = a1 - 2.f * a2;
    }
    si[t] = t;
    __syncthreads();
    for (int s = 128; s; s >>= 1) {
        if (t < s) {
            float o = sd[t + s]; int oi = si[t + s];
            if (o < sd[t] || (o == sd[t] && oi < si[t])) { sd[t] = o; si[t] = oi; }
        }
        __syncthreads();
    }
    int kb = si[0];
    if (t < D_) {
        float v = cb0[kb * D_ + t];
        g_xa[b * D_ + t] = v;
        out[OUT_SIDE + b * D_ + t] = v;       // side[0]
    }
    if (t == 0) out[OUT_CODES + b * M_] = (float)kb;
}

// ================= argmin select from fused dists =================
__global__ void k_argsel(float* __restrict__ out, int m) {
    int b = blockIdx.x, t = threadIdx.x;
    __shared__ float sd[256], sr[256];
    __shared__ int   si[256];
    __shared__ int   cnt;
    if (t == 0) cnt = 0;
    float d = g_dist[b * 256 + t];
    sd[t] = d; sr[t] = d; si[t] = t;
    __syncthreads();
    for (int s = 128; s; s >>= 1) {
        if (t < s) {
            float o = sr[t + s]; int oi = si[t + s];
            if (o < sr[t] || (o == sr[t] && oi < si[t])) { sr[t] = o; si[t] = oi; }
        }
        __syncthreads();
    }
    float d1 = sr[0];
    int   kb = si[0];
    if (sd[t] <= d1 + TAU) {
        int pos = atomicAdd(&cnt, 1);
        if (pos < 16) g_clist[b * 16 + pos] = t;
    }
    __syncthreads();
    if (t == 0) {
        g_ccount[b] = cnt;
        if (cnt == 1) {
            g_code[b] = kb;
            out[OUT_CODES + b * M_ + m + 1] = (float)kb;
        }
    }
}

// ================= exact fp32 rescue for near-ties =================
__global__ void k_ties(const float* __restrict__ x, const float* __restrict__ W1,
                       const float* __restrict__ W2, float* __restrict__ out,
                       int m, int ping) {
    int b = blockIdx.x;
    int C = g_ccount[b];
    if (C <= 1) return;
    const float* xin = ping ? g_xb : g_xa;
    int t = threadIdx.x, lane = t & 31, wid = t >> 5;
    __shared__ float xh[128], xv[128], h0s[256], z1s[128], h1s[256], z2s[128];
    __shared__ float red[8];
    __shared__ float bestd;
    __shared__ int   bestk;
    if (t < 128) { xh[t] = xin[b * 128 + t]; xv[t] = x[b * 128 + t]; }
    if (t == 0) { bestd = 3.4e38f; bestk = 0x7fffffff; }
    __syncthreads();
    bool all = (C > 16);
    int n = all ? 256 : C;
    const float* W2_0 = W2 + (2 * m) * 32768;
    const float* W1_1 = W1 + (2 * m + 1) * 32768;
    const float* W2_1 = W2 + (2 * m + 1) * 32768;
    for (int i = 0; i < n; ++i) {
        int k = all ? i : g_clist[b * 16 + i];
        h0s[t] = fmaxf(g_P1[(m * K_ + k) * H_ + t] + g_Q1[b * H_ + t], 0.f);
        __syncthreads();
        for (int it = 0; it < 16; ++it) {       // z1
            int d = it * 8 + wid;
            float a = 0.f;
            const float* wrow = W2_0 + d * 256;
#pragma unroll
            for (int j = 0; j < 8; ++j) a += wrow[lane + 32*j] * h0s[lane + 32*j];
#pragma unroll
            for (int o = 16; o; o >>= 1) a += __shfl_xor_sync(~0u, a, o);
            if (lane == 0) z1s[d] = g_cbz[(m * K_ + k) * D_ + d] + g_y[b * D_ + d] + a;
        }
        __syncthreads();
        for (int it = 0; it < 32; ++it) {       // h1
            int h = it * 8 + wid;
            float a = 0.f;
            const float* wrow = W1_1 + h * 128;
#pragma unroll
            for (int j = 0; j < 4; ++j) a += wrow[lane + 32*j] * z1s[lane + 32*j];
#pragma unroll
            for (int o = 16; o; o >>= 1) a += __shfl_xor_sync(~0u, a, o);
            if (lane == 0) h1s[h] = fmaxf(a, 0.f);
        }
        __syncthreads();
        for (int it = 0; it < 16; ++it) {       // z2
            int d = it * 8 + wid;
            float a = 0.f;
            const float* wrow = W2_1 + d * 256;
#pragma unroll
            for (int j = 0; j < 8; ++j) a += wrow[lane + 32*j] * h1s[lane + 32*j];
#pragma unroll
            for (int o = 16; o; o >>= 1) a += __shfl_xor_sync(~0u, a, o);
            if (lane == 0) z2s[d] = z1s[d] + a;
        }
        __syncthreads();
        float p = 0.f;
        if (t < 128) { float zf = z2s[t] + xh[t]; p = zf*zf - 2.f*xv[t]*zf; }
#pragma unroll
        for (int o = 16; o; o >>= 1) p += __shfl_xor_sync(~0u, p, o);
        if (lane == 0) red[wid] = p;
        __syncthreads();
        if (t == 0) {
            float d = red[0] + red[1] + red[2] + red[3];
            if (d < bestd || (d == bestd && k < bestk)) { bestd = d; bestk = k; }
        }
        __syncthreads();
    }
    if (t == 0) {
        g_code[b] = bestk;
        out[OUT_CODES + b * M_ + m + 1] = (float)bestk;
    }
}

extern "C" void kernel_launch(void* const* d_in, const int* in_sizes, int n_in,
                              void* d_out, int out_size) {
    const float* x   = (const float*)d_in[0];
    const float* cb0 = (const float*)d_in[1];
    const float* cbs = (const float*)d_in[2];
    const float* Wc  = (const float*)d_in[3];
    const float* bc  = (const float*)d_in[4];
    const float* W1  = (const float*)d_in[5];
    const float* W2  = (const float*)d_in[6];
    float* out = (float*)d_out;

    cudaFuncSetAttribute(k_fused, cudaFuncAttributeMaxDynamicSharedMemorySize, SMEM_F);

    // weight-only precomputes
    k_splitw<<<1792, 256>>>(W1, W2);
    k_cbzg<<<dim3(1, 2, 7), 256>>>(cbs, Wc, bc);
    k_p1g<<<dim3(2, 2, 7), 256>>>(W1);
    k_step0<<<BS_, 256>>>(x, cb0, out);

    int ping = 0;   // xhat currently in g_xa
    for (int m = 0; m < M_ - 1; ++m) {
        k_yg<<<dim3(1, 8), 256>>>(Wc, m, ping);
        k_q1g<<<dim3(2, 8), 256>>>(W1, m);
        // fused fast path: full 2-layer MLP + distances, one kernel
        k_fused<<<2048, 256, SMEM_F>>>(x, m, ping);
        // selection: fast dists + exact rescue for near-ties
        k_argsel<<<BS_, 256>>>(out, m);
        k_ties<<<BS_, 256>>>(x, W1, W2, out, m, ping);
        // exact fp32 winner recompute -> xhat, side, (final xhat)
        kw_h0<<<BS_, 256>>>(m);
        kw_g2<<<dim3(1, 8), 256>>>(W2, m);
        kw_g3<<<dim3(2, 8), 256>>>(W1, m);
        kw_g4<<<dim3(1, 8), 256>>>(W2, out, m, ping);
        ping ^= 1;
    }
}